// round 13
// baseline (speedup 1.0000x reference)
// R13: resubmission of R12 (broker infra failure, no kernel signal). 256x128 bmm tile.
#include <cuda_runtime.h>
#include <cuda_bf16.h>
#include <math.h>
#include <float.h>
#include <stdint.h>

#define BATCH 2
#define SEQ   8192
#define DIM   1024
#define HEADS 8
#define DHEAD 64
#define HDIM  512
#define QKVD  1536
#define WIN   64
#define NWIN  128
#define NSEL  1024
#define KVLEN 1025

// ---------------- scratch ----------------
__device__ float g_qkv[(size_t)BATCH*SEQ*QKVD];
__device__ float g_sq[BATCH*SEQ];
__device__ float g_skv[BATCH*SEQ];
__device__ int   g_idx[2*BATCH*NSEL];
__device__ float g_qh[(size_t)BATCH*NSEL*HDIM];
__device__ float g_kv[(size_t)BATCH*NSEL*DIM];
__device__ float g_k[(size_t)BATCH*HEADS*KVLEN*DHEAD];
__device__ float g_v[(size_t)BATCH*HEADS*KVLEN*DHEAD];
__device__ float g_ho[(size_t)BATCH*NSEL*DIM];
// bf16 split activations
__device__ __nv_bfloat16 g_xnh[(size_t)BATCH*SEQ*DIM],  g_xnl[(size_t)BATCH*SEQ*DIM];
__device__ __nv_bfloat16 g_lah[(size_t)BATCH*SEQ*HDIM], g_lal[(size_t)BATCH*SEQ*HDIM];
__device__ __nv_bfloat16 g_rth[(size_t)2*BATCH*NSEL*DIM], g_rtl[(size_t)2*BATCH*NSEL*DIM];
__device__ __nv_bfloat16 g_hah[(size_t)BATCH*NSEL*HDIM], g_hal[(size_t)BATCH*NSEL*HDIM];
// bf16 split weights, stored [N][K] (B^T)
__device__ __nv_bfloat16 w_qkvh[(size_t)QKVD*DIM], w_qkvl[(size_t)QKVD*DIM];
__device__ __nv_bfloat16 w_louth[(size_t)DIM*HDIM], w_loutl[(size_t)DIM*HDIM];
__device__ __nv_bfloat16 w_hqh[(size_t)HDIM*DIM],  w_hql[(size_t)HDIM*DIM];
__device__ __nv_bfloat16 w_hkvh[(size_t)DIM*DIM],  w_hkvl[(size_t)DIM*DIM];
__device__ __nv_bfloat16 w_houth[(size_t)DIM*HDIM], w_houtl[(size_t)DIM*HDIM];

// ---------------- helpers ----------------
__device__ __forceinline__ uint32_t smem_u32(const void* p) {
    uint32_t a;
    asm("{ .reg .u64 t; cvta.to.shared.u64 t, %1; cvt.u32.u64 %0, t; }" : "=r"(a) : "l"(p));
    return a;
}
#define SWZ64(o)  ((o) ^ (((o) >> 3) & 0x30))

__device__ __forceinline__ void ldm4(uint32_t* r, uint32_t addr) {
    asm volatile("ldmatrix.sync.aligned.m8n8.x4.shared.b16 {%0,%1,%2,%3}, [%4];"
        : "=r"(r[0]), "=r"(r[1]), "=r"(r[2]), "=r"(r[3]) : "r"(addr));
}
__device__ __forceinline__ void mma_bf16(float* d, const uint32_t* a, uint32_t b0, uint32_t b1) {
    asm volatile("mma.sync.aligned.m16n8k16.row.col.f32.bf16.bf16.f32 "
        "{%0,%1,%2,%3}, {%4,%5,%6,%7}, {%8,%9}, {%0,%1,%2,%3};"
        : "+f"(d[0]), "+f"(d[1]), "+f"(d[2]), "+f"(d[3])
        : "r"(a[0]), "r"(a[1]), "r"(a[2]), "r"(a[3]), "r"(b0), "r"(b1));
}
__device__ __forceinline__ void cpasync16(uint32_t dst, const void* src) {
    asm volatile("cp.async.cg.shared.global [%0], [%1], 16;" :: "r"(dst), "l"(src));
}
__device__ __forceinline__ void bf16split(float v, __nv_bfloat16* hi, __nv_bfloat16* lo) {
    __nv_bfloat16 h = __float2bfloat16(v);
    *hi = h;
    *lo = __float2bfloat16(v - __bfloat162float(h));
}

// ---------------- pipelined mma.sync split-bf16 GEMM: 256x128 tile, warp 64x64 ----------------
__global__ __launch_bounds__(256) void bmm_kernel(
        const __nv_bfloat16* __restrict__ Ah, const __nv_bfloat16* __restrict__ Al,
        const __nv_bfloat16* __restrict__ Bh, const __nv_bfloat16* __restrict__ Bl,
        float* __restrict__ C, int M, int N, int K, const float* __restrict__ bias) {
    extern __shared__ unsigned char dsm_raw[];
    unsigned char* sb = (unsigned char*)(((uintptr_t)dsm_raw + 1023) & ~(uintptr_t)1023);
    int t = threadIdx.x, wid = t >> 5, lane = t & 31;
    int n0 = blockIdx.x * 128, m0 = blockIdx.y * 256;
    uint32_t uS = smem_u32(sb);
    int wm = wid & 3, wn = wid >> 2;

    float acc[4][8][4];
#pragma unroll
    for (int m = 0; m < 4; m++)
#pragma unroll
        for (int n = 0; n < 8; n++)
#pragma unroll
            for (int q = 0; q < 4; q++) acc[m][n][q] = 0.f;

    int fr = lane & 15;
    uint32_t fb = (uint32_t)(lane >> 4) * 16;
    int nk = K >> 5;

    auto load_stage = [&](int s) {
        int k0 = s << 5;
        uint32_t stb = uS + (uint32_t)(s & 1) * 49152;
#pragma unroll
        for (int i = 0; i < 4; i++) {                 // A: 1024 chunks each array
            int e = t + i * 256;
            int r = e >> 2, c = e & 3;
            uint32_t so = SWZ64((uint32_t)(r * 64 + c * 16));
            size_t goA = (size_t)(m0 + r) * K + k0 + c * 8;
            cpasync16(stb + so,         Ah + goA);
            cpasync16(stb + 16384 + so, Al + goA);
        }
#pragma unroll
        for (int i = 0; i < 2; i++) {                 // B: 512 chunks each array
            int e = t + i * 256;
            int r = e >> 2, c = e & 3;
            uint32_t so = SWZ64((uint32_t)(r * 64 + c * 16));
            size_t goB = (size_t)(n0 + r) * K + k0 + c * 8;
            cpasync16(stb + 32768 + so, Bh + goB);
            cpasync16(stb + 40960 + so, Bl + goB);
        }
        asm volatile("cp.async.commit_group;" ::: "memory");
    };

    load_stage(0);
    for (int s = 0; s < nk; s++) {
        if (s + 1 < nk) {
            load_stage(s + 1);
            asm volatile("cp.async.wait_group 1;" ::: "memory");
        } else {
            asm volatile("cp.async.wait_group 0;" ::: "memory");
        }
        __syncthreads();
        uint32_t stb = uS + (uint32_t)(s & 1) * 49152;
        uint32_t uAh = stb, uAl = stb + 16384, uBh = stb + 32768, uBl = stb + 40960;
#pragma unroll
        for (int kk = 0; kk < 2; kk++) {
            uint32_t kb = (uint32_t)kk * 32 + fb;
            uint32_t ah[4][4], al[4][4];
#pragma unroll
            for (int mt = 0; mt < 4; mt++) {
                uint32_t ro = (uint32_t)(wm*64 + mt*16 + fr) * 64 + kb;
                ldm4(ah[mt], uAh + SWZ64(ro));
                ldm4(al[mt], uAl + SWZ64(ro));
            }
#pragma unroll
            for (int np = 0; np < 4; np++) {
                uint32_t bh[4], bl[4];
                uint32_t rno = (uint32_t)(wn*64 + np*16 + fr) * 64 + kb;
                ldm4(bh, uBh + SWZ64(rno));
                ldm4(bl, uBl + SWZ64(rno));
#pragma unroll
                for (int mt = 0; mt < 4; mt++) {
                    mma_bf16(acc[mt][np*2],   ah[mt], bh[0], bh[2]);
                    mma_bf16(acc[mt][np*2+1], ah[mt], bh[1], bh[3]);
                    mma_bf16(acc[mt][np*2],   ah[mt], bl[0], bl[2]);
                    mma_bf16(acc[mt][np*2+1], ah[mt], bl[1], bl[3]);
                    mma_bf16(acc[mt][np*2],   al[mt], bh[0], bh[2]);
                    mma_bf16(acc[mt][np*2+1], al[mt], bh[1], bh[3]);
                }
            }
        }
        __syncthreads();
    }

    int qrow = lane >> 2, qcol = (lane & 3) * 2;
#pragma unroll
    for (int mt = 0; mt < 4; mt++) {
        int row0 = m0 + wm*64 + mt*16 + qrow;
#pragma unroll
        for (int nt = 0; nt < 8; nt++) {
            int col = n0 + wn*64 + nt*8 + qcol;
            float b0 = bias ? bias[col] : 0.f;
            float b1 = bias ? bias[col+1] : 0.f;
            float2 v0 = make_float2(acc[mt][nt][0] + b0, acc[mt][nt][1] + b1);
            float2 v1 = make_float2(acc[mt][nt][2] + b0, acc[mt][nt][3] + b1);
            *(float2*)(C + (size_t)row0 * N + col) = v0;
            *(float2*)(C + (size_t)(row0 + 8) * N + col) = v1;
        }
    }
}

// ---------------- weight prep ----------------
__global__ void wprep_t_kernel(const float* __restrict__ W, __nv_bfloat16* __restrict__ Th,
                               __nv_bfloat16* __restrict__ Tl, int K, int N) {
    __shared__ float tile[32][33];
    int k0 = blockIdx.x * 32, n0 = blockIdx.y * 32;
    int tx = threadIdx.x, ty = threadIdx.y;
    for (int j = 0; j < 32; j += 8)
        tile[ty + j][tx] = W[(size_t)(k0 + ty + j) * N + n0 + tx];
    __syncthreads();
    for (int j = 0; j < 32; j += 8) {
        float v = tile[tx][ty + j];
        size_t o = (size_t)(n0 + ty + j) * K + k0 + tx;
        __nv_bfloat16 h, l; bf16split(v, &h, &l);
        Th[o] = h; Tl[o] = l;
    }
}
__global__ void wprep_kernel(const float* __restrict__ W, __nv_bfloat16* __restrict__ H,
                             __nv_bfloat16* __restrict__ L, int n) {
    int i = blockIdx.x * 256 + threadIdx.x;
    if (i < n) { __nv_bfloat16 h, l; bf16split(W[i], &h, &l); H[i] = h; L[i] = l; }
}

// ---------------- layernorm -> bf16 split ----------------
__global__ void ln_kernel(const float* __restrict__ x, const float* __restrict__ g,
                          const float* __restrict__ bta) {
    int row = blockIdx.x;
    const float* xr = x + (size_t)row * DIM;
    int t = threadIdx.x;
    float v[4]; float s = 0.f;
#pragma unroll
    for (int i = 0; i < 4; i++) { v[i] = xr[t + 256*i]; s += v[i]; }
    __shared__ float red[256];
    red[t] = s; __syncthreads();
    for (int k = 128; k > 0; k >>= 1) { if (t < k) red[t] += red[t+k]; __syncthreads(); }
    float mu = red[0] * (1.0f/DIM); __syncthreads();
    float s2 = 0.f;
#pragma unroll
    for (int i = 0; i < 4; i++) { float d = v[i]-mu; s2 += d*d; }
    red[t] = s2; __syncthreads();
    for (int k = 128; k > 0; k >>= 1) { if (t < k) red[t] += red[t+k]; __syncthreads(); }
    float inv = 1.0f / sqrtf(red[0] * (1.0f/DIM) + 1e-5f);
#pragma unroll
    for (int i = 0; i < 4; i++) {
        int d = t + 256*i;
        float y = (v[i]-mu)*inv*g[d] + bta[d];
        __nv_bfloat16 h, l; bf16split(y, &h, &l);
        g_xnh[(size_t)row*DIM + d] = h;
        g_xnl[(size_t)row*DIM + d] = l;
    }
}

// ---------------- light attention: 3x64 chunks, online softmax, 4x4 reg blocking ----------------
__global__ __launch_bounds__(256) void light_attn_kernel() {
    extern __shared__ float lsm[];
    float* sq = lsm;
    float* sk = sq + 64*65;
    float* sv = sk + 64*65;
    float* sp = sv + 64*65;
    int win = blockIdx.x, h = blockIdx.y, b = blockIdx.z;
    int t = threadIdx.x;
    for (int e = t; e < 64*64; e += 256) {
        int i = e >> 6, d = e & 63;
        int n = win*64 + i;
        sq[i*65 + d] = g_qkv[((size_t)(b*SEQ + n))*QKVD + h*64 + d] * 0.125f;
    }
    int qg = t >> 4, kg = t & 15;
    float m[4], l[4], acc[4][4];
#pragma unroll
    for (int u = 0; u < 4; u++) {
        m[u] = -FLT_MAX; l[u] = 0.f;
#pragma unroll
        for (int w = 0; w < 4; w++) acc[u][w] = 0.f;
    }

    for (int c = 0; c < 3; c++) {
        int nbase = (win - 1 + c) * 64;
        __syncthreads();
        for (int e = t; e < 64*64; e += 256) {
            int j = e >> 6, d = e & 63;
            int n = nbase + j;
            bool ok = (n >= 0 && n < SEQ);
            size_t base = ((size_t)(b*SEQ + n))*QKVD + h*64 + d;
            sk[j*65 + d] = ok ? g_qkv[base + 512]  : 0.f;
            sv[j*65 + d] = ok ? g_qkv[base + 1024] : 0.f;
        }
        __syncthreads();
        float s[4][4];
#pragma unroll
        for (int u = 0; u < 4; u++)
#pragma unroll
            for (int w = 0; w < 4; w++) s[u][w] = 0.f;
        for (int d = 0; d < 64; d++) {
            float qv[4], kv[4];
#pragma unroll
            for (int u = 0; u < 4; u++) qv[u] = sq[(qg + 16*u)*65 + d];
#pragma unroll
            for (int w = 0; w < 4; w++) kv[w] = sk[(kg + 16*w)*65 + d];
#pragma unroll
            for (int u = 0; u < 4; u++)
#pragma unroll
                for (int w = 0; w < 4; w++) s[u][w] = fmaf(qv[u], kv[w], s[u][w]);
        }
#pragma unroll
        for (int u = 0; u < 4; u++) {
            int iabs = win*64 + qg + 16*u;
            float cm = -FLT_MAX;
#pragma unroll
            for (int w = 0; w < 4; w++) {
                int jabs = nbase + kg + 16*w;
                bool valid = (jabs >= 0) && (jabs < SEQ) && (abs(iabs - jabs) <= WIN);
                float sx = valid ? s[u][w] : -FLT_MAX;
                s[u][w] = sx;
                cm = fmaxf(cm, sx);
            }
#pragma unroll
            for (int off = 1; off < 16; off <<= 1)
                cm = fmaxf(cm, __shfl_xor_sync(0xFFFFFFFFu, cm, off));
            float mn = fmaxf(m[u], cm);
            float scale = expf(m[u] - mn);
            bool anyvalid = (mn != -FLT_MAX);
            float ls = 0.f;
#pragma unroll
            for (int w = 0; w < 4; w++) {
                float p = anyvalid ? expf(s[u][w] - mn) : 0.f;
                sp[(qg + 16*u)*65 + kg + 16*w] = p;
                ls += p;
            }
#pragma unroll
            for (int off = 1; off < 16; off <<= 1)
                ls += __shfl_xor_sync(0xFFFFFFFFu, ls, off);
            l[u] = l[u]*scale + ls;
            m[u] = mn;
#pragma unroll
            for (int w = 0; w < 4; w++) acc[u][w] *= scale;
        }
        __syncwarp();
        for (int k = 0; k < 64; k++) {
            float pv[4], vv[4];
#pragma unroll
            for (int u = 0; u < 4; u++) pv[u] = sp[(qg + 16*u)*65 + k];
#pragma unroll
            for (int w = 0; w < 4; w++) vv[w] = sv[k*65 + kg + 16*w];
#pragma unroll
            for (int u = 0; u < 4; u++)
#pragma unroll
                for (int w = 0; w < 4; w++) acc[u][w] = fmaf(pv[u], vv[w], acc[u][w]);
        }
        __syncwarp();
    }
#pragma unroll
    for (int u = 0; u < 4; u++) {
        float invl = 1.0f / l[u];
        int iabs = win*64 + qg + 16*u;
#pragma unroll
        for (int w = 0; w < 4; w++) {
            float y = acc[u][w] * invl;
            size_t o = ((size_t)(b*SEQ + iabs))*HDIM + h*64 + kg + 16*w;
            __nv_bfloat16 hh, ll; bf16split(y, &hh, &ll);
            g_lah[o] = hh; g_lal[o] = ll;
        }
    }
}

// ---------------- routing scores ----------------
__global__ void route_score_kernel(const float* __restrict__ x,
                                   const float* __restrict__ qt,
                                   const float* __restrict__ kt) {
    int row = blockIdx.x;
    int t = threadIdx.x;
    const float* xr = x + (size_t)row * DIM;
    float sq = 0.f, sk = 0.f;
#pragma unroll
    for (int i = t; i < DIM; i += 256) {
        float v = xr[i];
        sq = fmaf(v, qt[i], sq);
        sk = fmaf(v, kt[i], sk);
    }
    __shared__ float r1[256], r2[256];
    r1[t] = sq; r2[t] = sk; __syncthreads();
    for (int k = 128; k > 0; k >>= 1) {
        if (t < k) { r1[t] += r1[t+k]; r2[t] += r2[t+k]; }
        __syncthreads();
    }
    if (t == 0) { g_sq[row] = r1[0]; g_skv[row] = r2[0]; }
}

// ---------------- coordinate descent + exact top-k (bitonic) ----------------
__global__ __launch_bounds__(1024) void route_select_kernel() {
    extern __shared__ unsigned char rsm[];
    unsigned long long* key = (unsigned long long*)rsm;
    float* s  = (float*)(key + SEQ);
    float* bb = s + SEQ;
    __shared__ float red[1024];
    int b = blockIdx.x, which = blockIdx.y;
    int t = threadIdx.x;
    const float* src = which ? g_skv : g_sq;
    for (int i = t; i < SEQ; i += 1024) { float v = src[b*SEQ + i]; s[i] = v; bb[i] = -v; }
    __syncthreads();
    float cur = 4.0f;
    const float logk = logf(1152.0f);
    float a = 0.f;
    for (int it = 0; it < 20; it++) {
        float m = -FLT_MAX;
        for (int i = t; i < SEQ; i += 1024) m = fmaxf(m, (s[i] + bb[i]) / cur);
        red[t] = m; __syncthreads();
        for (int k = 512; k > 0; k >>= 1) { if (t < k) red[t] = fmaxf(red[t], red[t+k]); __syncthreads(); }
        m = red[0]; __syncthreads();
        float sum = 0.f;
        for (int i = t; i < SEQ; i += 1024) sum += expf((s[i] + bb[i]) / cur - m);
        red[t] = sum; __syncthreads();
        for (int k = 512; k > 0; k >>= 1) { if (t < k) red[t] += red[t+k]; __syncthreads(); }
        float lse = m + logf(red[0]);
        a = cur * (logk - lse);
        __syncthreads();
        for (int i = t; i < SEQ; i += 1024) bb[i] = -fmaxf(s[i] + a, 0.f);
        cur = fmaxf(cur * 0.7f, 0.03f);
        __syncthreads();
    }
    for (int i = t; i < SEQ; i += 1024) {
        float ta = s[i] + a;
        float sc = expf((ta + bb[i]) / cur);
        unsigned int sb = __float_as_uint(sc);
        key[i] = ((unsigned long long)sb << 32)
               | (unsigned long long)(0xFFFFFFFFu - (unsigned)i);
    }
    __syncthreads();
    for (int size = 2; size <= SEQ; size <<= 1) {
        for (int stride = size >> 1; stride > 0; stride >>= 1) {
            for (int i = t; i < SEQ; i += 1024) {
                int j = i ^ stride;
                if (j > i) {
                    bool desc = ((i & size) == 0);
                    unsigned long long ki = key[i], kj = key[j];
                    if ((ki < kj) == desc) { key[i] = kj; key[j] = ki; }
                }
            }
            __syncthreads();
        }
    }
    if (t < NSEL) {
        unsigned idxv = 0xFFFFFFFFu - (unsigned)(key[t] & 0xFFFFFFFFull);
        g_idx[(which*BATCH + b)*NSEL + t] = (int)idxv;
    }
}

// ---------------- gather routed + rmsnorm -> bf16 split ----------------
__global__ void gather_rms_kernel(const float* __restrict__ x,
                                  const float* __restrict__ gamma) {
    int j = blockIdx.x, b = blockIdx.y, which = blockIdx.z;
    int idx = g_idx[(which*BATCH + b)*NSEL + j];
    const float* xr = x + ((size_t)b*SEQ + idx)*DIM;
    int t = threadIdx.x;
    float v[4]; float ss = 0.f;
#pragma unroll
    for (int i = 0; i < 4; i++) { v[i] = xr[t + 256*i]; ss += v[i]*v[i]; }
    __shared__ float red[256];
    red[t] = ss; __syncthreads();
    for (int k = 128; k > 0; k >>= 1) { if (t < k) red[t] += red[t+k]; __syncthreads(); }
    float nrm = sqrtf(red[0]);
    float scale = 32.0f / fmaxf(nrm, 1e-12f);
    size_t base = (((size_t)which*BATCH + b)*NSEL + j)*DIM;
#pragma unroll
    for (int i = 0; i < 4; i++) {
        int d = t + 256*i;
        float y = v[i]*scale*gamma[d];
        __nv_bfloat16 h, l; bf16split(y, &h, &l);
        g_rth[base + d] = h; g_rtl[base + d] = l;
    }
}

// ---------------- rope on heavy q ----------------
__global__ void rope_q_kernel() {
    int e = blockIdx.x*256 + threadIdx.x;
    int d = e & 31;
    int h = (e >> 5) & 7;
    int j = (e >> 8) & 1023;
    int b = e >> 18;
    int tpos = g_idx[b*NSEL + j];
    float invf = powf(10000.0f, -(float)d / 32.0f);
    float th = (float)tpos * invf;
    float c, sn; sincosf(th, &sn, &c);
    size_t base = ((size_t)(b*NSEL + j))*HDIM + h*DHEAD;
    float x1 = g_qh[base + d], x2 = g_qh[base + d + 32];
    g_qh[base + d]      = x1*c - x2*sn;
    g_qh[base + d + 32] = x2*c + x1*sn;
}

// ---------------- pack k/v with rope + null kv ----------------
__global__ void pack_kv_kernel(const float* __restrict__ null_kv) {
    int e = blockIdx.x*256 + threadIdx.x;
    if (e >= BATCH*HEADS*KVLEN*32) return;
    int d  = e & 31;
    int jj = (e >> 5) % KVLEN;
    int hb = (e >> 5) / KVLEN;
    int h = hb & 7, b = hb >> 3;
    size_t obase = ((size_t)(b*HEADS + h)*KVLEN + jj)*DHEAD;
    if (jj == 0) {
        g_k[obase + d]      = null_kv[h*DHEAD + d];
        g_k[obase + d + 32] = null_kv[h*DHEAD + d + 32];
        g_v[obase + d]      = null_kv[HEADS*DHEAD + h*DHEAD + d];
        g_v[obase + d + 32] = null_kv[HEADS*DHEAD + h*DHEAD + d + 32];
    } else {
        int j = jj - 1;
        int tpos = g_idx[(BATCH + b)*NSEL + j];
        size_t ibase = ((size_t)(b*NSEL + j))*DIM + h*128;
        float k1 = g_kv[ibase + d], k2 = g_kv[ibase + d + 32];
        float invf = powf(10000.0f, -(float)d / 32.0f);
        float th = (float)tpos * invf;
        float c, sn; sincosf(th, &sn, &c);
        g_k[obase + d]      = k1*c - k2*sn;
        g_k[obase + d + 32] = k2*c + k1*sn;
        g_v[obase + d]      = g_kv[ibase + 64 + d];
        g_v[obase + d + 32] = g_kv[ibase + 64 + d + 32];
    }
}

// ---------------- heavy attention: 64-key chunks, 4x4 reg blocking ----------------
__global__ __launch_bounds__(256) void heavy_attn_kernel() {
    extern __shared__ float hsm[];
    float* sq = hsm;
    float* sk = sq + 64*65;
    float* sv = sk + 64*65;
    float* sp = sv + 64*65;
    int qt = blockIdx.x, h = blockIdx.y, b = blockIdx.z;
    int t = threadIdx.x;
    for (int e = t; e < 64*64; e += 256) {
        int i = e >> 6, d = e & 63;
        sq[i*65 + d] = g_qh[((size_t)(b*NSEL + qt*64 + i))*HDIM + h*64 + d] * 0.125f;
    }
    int qg = t >> 4, kg = t & 15;
    float m[4], l[4], acc[4][4];
#pragma unroll
    for (int u = 0; u < 4; u++) {
        m[u] = -FLT_MAX; l[u] = 0.f;
#pragma unroll
        for (int w = 0; w < 4; w++) acc[u][w] = 0.f;
    }
    size_t kvbase = ((size_t)(b*HEADS + h))*KVLEN*DHEAD;
    for (int c0 = 0; c0 < KVLEN; c0 += 64) {
        int cnt = min(64, KVLEN - c0);
        __syncthreads();
        for (int e = t; e < 64*64; e += 256) {
            int j = e >> 6, d = e & 63;
            bool ok = j < cnt;
            sk[j*65 + d] = ok ? g_k[kvbase + (size_t)(c0 + j)*DHEAD + d] : 0.f;
            sv[j*65 + d] = ok ? g_v[kvbase + (size_t)(c0 + j)*DHEAD + d] : 0.f;
        }
        __syncthreads();
        float s[4][4];
#pragma unroll
        for (int u = 0; u < 4; u++)
#pragma unroll
            for (int w = 0; w < 4; w++) s[u][w] = 0.f;
        for (int d = 0; d < 64; d++) {
            float qv[4], kv[4];
#pragma unroll
            for (int u = 0; u < 4; u++) qv[u] = sq[(qg + 16*u)*65 + d];
#pragma unroll
            for (int w = 0; w < 4; w++) kv[w] = sk[(kg + 16*w)*65 + d];
#pragma unroll
            for (int u = 0; u < 4; u++)
#pragma unroll
                for (int w = 0; w < 4; w++) s[u][w] = fmaf(qv[u], kv[w], s[u][w]);
        }
#pragma unroll
        for (int u = 0; u < 4; u++) {
            float cm = -FLT_MAX;
#pragma unroll
            for (int w = 0; w < 4; w++) {
                float sx = (kg + 16*w < cnt) ? s[u][w] : -FLT_MAX;
                s[u][w] = sx;
                cm = fmaxf(cm, sx);
            }
#pragma unroll
            for (int off = 1; off < 16; off <<= 1)
                cm = fmaxf(cm, __shfl_xor_sync(0xFFFFFFFFu, cm, off));
            float mn = fmaxf(m[u], cm);
            float scale = expf(m[u] - mn);
            float ls = 0.f;
#pragma unroll
            for (int w = 0; w < 4; w++) {
                float p = expf(s[u][w] - mn);
                sp[(qg + 16*u)*65 + kg + 16*w] = p;
                ls += p;
            }
#pragma unroll
            for (int off = 1; off < 16; off <<= 1)
                ls += __shfl_xor_sync(0xFFFFFFFFu, ls, off);
            l[u] = l[u]*scale + ls;
            m[u] = mn;
#pragma unroll
            for (int w = 0; w < 4; w++) acc[u][w] *= scale;
        }
        __syncwarp();
        for (int k = 0; k < 64; k++) {
            float pv[4], vv[4];
#pragma unroll
            for (int u = 0; u < 4; u++) pv[u] = sp[(qg + 16*u)*65 + k];
#pragma unroll
            for (int w = 0; w < 4; w++) vv[w] = sv[k*65 + kg + 16*w];
#pragma unroll
            for (int u = 0; u < 4; u++)
#pragma unroll
                for (int w = 0; w < 4; w++) acc[u][w] = fmaf(pv[u], vv[w], acc[u][w]);
        }
        __syncwarp();
    }
#pragma unroll
    for (int u = 0; u < 4; u++) {
        float invl = 1.0f / l[u];
#pragma unroll
        for (int w = 0; w < 4; w++) {
            float y = acc[u][w] * invl;
            size_t o = ((size_t)(b*NSEL + qt*64 + qg + 16*u))*HDIM + h*64 + kg + 16*w;
            __nv_bfloat16 hh, ll; bf16split(y, &hh, &ll);
            g_hah[o] = hh; g_hal[o] = ll;
        }
    }
}

// ---------------- scatter ----------------
__global__ void scatter_kernel(float* __restrict__ out, const float* __restrict__ nullq) {
    int j = blockIdx.x & 1023, b = blockIdx.x >> 10;
    int i = g_idx[b*NSEL + j];
    float* orow = out + ((size_t)b*SEQ + i)*DIM;
    const float* hrow = g_ho + ((size_t)(b*NSEL + j))*DIM;
    for (int d = threadIdx.x; d < DIM; d += 256)
        orow[d] += hrow[d] - nullq[d];
}

// ---------------- launch ----------------
extern "C" void kernel_launch(void* const* d_in, const int* in_sizes, int n_in,
                              void* d_out, int out_size) {
    const float* x       = (const float*)d_in[0];
    const float* ln_g    = (const float*)d_in[1];
    const float* ln_b    = (const float*)d_in[2];
    const float* qkv_w   = (const float*)d_in[3];
    const float* lout_w  = (const float*)d_in[4];
    const float* q_tok   = (const float*)d_in[5];
    const float* kv_tok  = (const float*)d_in[6];
    const float* hgamma  = (const float*)d_in[7];
    const float* hq_w    = (const float*)d_in[8];
    const float* hkv_w   = (const float*)d_in[9];
    const float* hnullkv = (const float*)d_in[10];
    const float* hout_w  = (const float*)d_in[11];
    const float* nullq   = (const float*)d_in[12];
    float* out = (float*)d_out;

    static cudaStream_t s2 = nullptr;
    static cudaEvent_t evFork = nullptr, evJoin = nullptr;
    if (!s2) {
        cudaStreamCreateWithFlags(&s2, cudaStreamNonBlocking);
        cudaEventCreateWithFlags(&evFork, cudaEventDisableTiming);
        cudaEventCreateWithFlags(&evJoin, cudaEventDisableTiming);
    }

    float *p_qkv, *p_qh, *p_kv, *p_ho;
    __nv_bfloat16 *p_xnh, *p_xnl, *p_lah, *p_lal, *p_rth, *p_rtl, *p_hah, *p_hal;
    __nv_bfloat16 *p_wqh, *p_wql, *p_wlh, *p_wll, *p_whqh, *p_whql, *p_wkh, *p_wkl, *p_woh, *p_wol;
    cudaGetSymbolAddress((void**)&p_qkv, g_qkv);
    cudaGetSymbolAddress((void**)&p_qh, g_qh);
    cudaGetSymbolAddress((void**)&p_kv, g_kv);
    cudaGetSymbolAddress((void**)&p_ho, g_ho);
    cudaGetSymbolAddress((void**)&p_xnh, g_xnh); cudaGetSymbolAddress((void**)&p_xnl, g_xnl);
    cudaGetSymbolAddress((void**)&p_lah, g_lah); cudaGetSymbolAddress((void**)&p_lal, g_lal);
    cudaGetSymbolAddress((void**)&p_rth, g_rth); cudaGetSymbolAddress((void**)&p_rtl, g_rtl);
    cudaGetSymbolAddress((void**)&p_hah, g_hah); cudaGetSymbolAddress((void**)&p_hal, g_hal);
    cudaGetSymbolAddress((void**)&p_wqh, w_qkvh); cudaGetSymbolAddress((void**)&p_wql, w_qkvl);
    cudaGetSymbolAddress((void**)&p_wlh, w_louth); cudaGetSymbolAddress((void**)&p_wll, w_loutl);
    cudaGetSymbolAddress((void**)&p_whqh, w_hqh); cudaGetSymbolAddress((void**)&p_whql, w_hql);
    cudaGetSymbolAddress((void**)&p_wkh, w_hkvh); cudaGetSymbolAddress((void**)&p_wkl, w_hkvl);
    cudaGetSymbolAddress((void**)&p_woh, w_houth); cudaGetSymbolAddress((void**)&p_wol, w_houtl);

    const int LSMEM = 4*64*65*4;
    const int HSMEM = 4*64*65*4;
    const int RSMEM = SEQ*8 + 2*SEQ*4;
    const int GSMEM = 98304 + 1024;
    cudaFuncSetAttribute(light_attn_kernel,  cudaFuncAttributeMaxDynamicSharedMemorySize, LSMEM);
    cudaFuncSetAttribute(heavy_attn_kernel,  cudaFuncAttributeMaxDynamicSharedMemorySize, HSMEM);
    cudaFuncSetAttribute(route_select_kernel, cudaFuncAttributeMaxDynamicSharedMemorySize, RSMEM);
    cudaFuncSetAttribute(bmm_kernel, cudaFuncAttributeMaxDynamicSharedMemorySize, GSMEM);

    cudaEventRecord(evFork, 0);
    cudaStreamWaitEvent(s2, evFork, 0);

    // ======== stream 0: light path ========
    wprep_t_kernel<<<dim3(DIM/32, QKVD/32), dim3(32,8)>>>(qkv_w, p_wqh, p_wql, DIM, QKVD);
    ln_kernel<<<BATCH*SEQ, 256>>>(x, ln_g, ln_b);
    bmm_kernel<<<dim3(QKVD/128, (BATCH*SEQ)/256), 256, GSMEM>>>(
        p_xnh, p_xnl, p_wqh, p_wql, p_qkv, BATCH*SEQ, QKVD, DIM, nullptr);
    light_attn_kernel<<<dim3(NWIN, HEADS, BATCH), 256, LSMEM>>>();
    wprep_t_kernel<<<dim3(HDIM/32, DIM/32), dim3(32,8)>>>(lout_w, p_wlh, p_wll, HDIM, DIM);
    bmm_kernel<<<dim3(DIM/128, (BATCH*SEQ)/256), 256, GSMEM>>>(
        p_lah, p_lal, p_wlh, p_wll, out, BATCH*SEQ, DIM, HDIM, nullq);

    // ======== stream s2: routing + heavy path ========
    wprep_kernel<<<(DIM*DIM + 255)/256, 256, 0, s2>>>(hkv_w, p_wkh, p_wkl, DIM*DIM);
    wprep_t_kernel<<<dim3(DIM/32, HDIM/32), dim3(32,8), 0, s2>>>(hq_w, p_whqh, p_whql, DIM, HDIM);
    wprep_t_kernel<<<dim3(HDIM/32, DIM/32), dim3(32,8), 0, s2>>>(hout_w, p_woh, p_wol, HDIM, DIM);
    route_score_kernel<<<BATCH*SEQ, 256, 0, s2>>>(x, q_tok, kv_tok);
    route_select_kernel<<<dim3(BATCH, 2), 1024, RSMEM, s2>>>();
    gather_rms_kernel<<<dim3(NSEL, BATCH, 2), 256, 0, s2>>>(x, hgamma);
    bmm_kernel<<<dim3(HDIM/128, (BATCH*NSEL)/256), 256, GSMEM, s2>>>(
        p_rth, p_rtl, p_whqh, p_whql, p_qh, BATCH*NSEL, HDIM, DIM, nullptr);
    rope_q_kernel<<<(BATCH*NSEL*HEADS*32)/256, 256, 0, s2>>>();
    bmm_kernel<<<dim3(DIM/128, (BATCH*NSEL)/256), 256, GSMEM, s2>>>(
        p_rth + (size_t)BATCH*NSEL*DIM, p_rtl + (size_t)BATCH*NSEL*DIM,
        p_wkh, p_wkl, p_kv, BATCH*NSEL, DIM, DIM, nullptr);
    pack_kv_kernel<<<(BATCH*HEADS*KVLEN*32 + 255)/256, 256, 0, s2>>>(hnullkv);
    heavy_attn_kernel<<<dim3(16, HEADS, BATCH), 256, HSMEM, s2>>>();
    bmm_kernel<<<dim3(DIM/128, (BATCH*NSEL)/256), 256, GSMEM, s2>>>(
        p_hah, p_hal, p_woh, p_wol, p_ho, BATCH*NSEL, DIM, HDIM, nullptr);

    cudaEventRecord(evJoin, s2);
    cudaStreamWaitEvent(0, evJoin, 0);
    scatter_kernel<<<BATCH*NSEL, 256>>>(out, nullq);
}

// round 14
// speedup vs baseline: 1.1472x; 1.1472x over previous
// R14: revert bmm to R11 128x128 tile (256x128 regressed: 1-CTA/SM by regs); add minBlocksPerSM=2 pin.
#include <cuda_runtime.h>
#include <cuda_bf16.h>
#include <math.h>
#include <float.h>
#include <stdint.h>

#define BATCH 2
#define SEQ   8192
#define DIM   1024
#define HEADS 8
#define DHEAD 64
#define HDIM  512
#define QKVD  1536
#define WIN   64
#define NWIN  128
#define NSEL  1024
#define KVLEN 1025

// ---------------- scratch ----------------
__device__ float g_qkv[(size_t)BATCH*SEQ*QKVD];
__device__ float g_sq[BATCH*SEQ];
__device__ float g_skv[BATCH*SEQ];
__device__ int   g_idx[2*BATCH*NSEL];
__device__ float g_qh[(size_t)BATCH*NSEL*HDIM];
__device__ float g_kv[(size_t)BATCH*NSEL*DIM];
__device__ float g_k[(size_t)BATCH*HEADS*KVLEN*DHEAD];
__device__ float g_v[(size_t)BATCH*HEADS*KVLEN*DHEAD];
__device__ float g_ho[(size_t)BATCH*NSEL*DIM];
// bf16 split activations
__device__ __nv_bfloat16 g_xnh[(size_t)BATCH*SEQ*DIM],  g_xnl[(size_t)BATCH*SEQ*DIM];
__device__ __nv_bfloat16 g_lah[(size_t)BATCH*SEQ*HDIM], g_lal[(size_t)BATCH*SEQ*HDIM];
__device__ __nv_bfloat16 g_rth[(size_t)2*BATCH*NSEL*DIM], g_rtl[(size_t)2*BATCH*NSEL*DIM];
__device__ __nv_bfloat16 g_hah[(size_t)BATCH*NSEL*HDIM], g_hal[(size_t)BATCH*NSEL*HDIM];
// bf16 split weights, stored [N][K] (B^T)
__device__ __nv_bfloat16 w_qkvh[(size_t)QKVD*DIM], w_qkvl[(size_t)QKVD*DIM];
__device__ __nv_bfloat16 w_louth[(size_t)DIM*HDIM], w_loutl[(size_t)DIM*HDIM];
__device__ __nv_bfloat16 w_hqh[(size_t)HDIM*DIM],  w_hql[(size_t)HDIM*DIM];
__device__ __nv_bfloat16 w_hkvh[(size_t)DIM*DIM],  w_hkvl[(size_t)DIM*DIM];
__device__ __nv_bfloat16 w_houth[(size_t)DIM*HDIM], w_houtl[(size_t)DIM*HDIM];

// ---------------- helpers ----------------
__device__ __forceinline__ uint32_t smem_u32(const void* p) {
    uint32_t a;
    asm("{ .reg .u64 t; cvta.to.shared.u64 t, %1; cvt.u32.u64 %0, t; }" : "=r"(a) : "l"(p));
    return a;
}
#define SWZ64(o)  ((o) ^ (((o) >> 3) & 0x30))

__device__ __forceinline__ void ldm4(uint32_t* r, uint32_t addr) {
    asm volatile("ldmatrix.sync.aligned.m8n8.x4.shared.b16 {%0,%1,%2,%3}, [%4];"
        : "=r"(r[0]), "=r"(r[1]), "=r"(r[2]), "=r"(r[3]) : "r"(addr));
}
__device__ __forceinline__ void mma_bf16(float* d, const uint32_t* a, uint32_t b0, uint32_t b1) {
    asm volatile("mma.sync.aligned.m16n8k16.row.col.f32.bf16.bf16.f32 "
        "{%0,%1,%2,%3}, {%4,%5,%6,%7}, {%8,%9}, {%0,%1,%2,%3};"
        : "+f"(d[0]), "+f"(d[1]), "+f"(d[2]), "+f"(d[3])
        : "r"(a[0]), "r"(a[1]), "r"(a[2]), "r"(a[3]), "r"(b0), "r"(b1));
}
__device__ __forceinline__ void cpasync16(uint32_t dst, const void* src) {
    asm volatile("cp.async.cg.shared.global [%0], [%1], 16;" :: "r"(dst), "l"(src));
}
__device__ __forceinline__ void bf16split(float v, __nv_bfloat16* hi, __nv_bfloat16* lo) {
    __nv_bfloat16 h = __float2bfloat16(v);
    *hi = h;
    *lo = __float2bfloat16(v - __bfloat162float(h));
}

// ---------------- pipelined mma.sync split-bf16 GEMM: 128x128 tile, warp 32x64 ----------------
__global__ __launch_bounds__(256, 2) void bmm_kernel(
        const __nv_bfloat16* __restrict__ Ah, const __nv_bfloat16* __restrict__ Al,
        const __nv_bfloat16* __restrict__ Bh, const __nv_bfloat16* __restrict__ Bl,
        float* __restrict__ C, int M, int N, int K, const float* __restrict__ bias) {
    extern __shared__ unsigned char dsm_raw[];
    unsigned char* sb = (unsigned char*)(((uintptr_t)dsm_raw + 1023) & ~(uintptr_t)1023);
    int t = threadIdx.x, wid = t >> 5, lane = t & 31;
    int n0 = blockIdx.x * 128, m0 = blockIdx.y * 128;
    uint32_t uS = smem_u32(sb);
    int wm = wid & 3, wn = wid >> 2;

    float acc[2][8][4];
#pragma unroll
    for (int m = 0; m < 2; m++)
#pragma unroll
        for (int n = 0; n < 8; n++)
#pragma unroll
            for (int q = 0; q < 4; q++) acc[m][n][q] = 0.f;

    int fr = lane & 15;
    uint32_t fb = (uint32_t)(lane >> 4) * 16;
    int nk = K >> 5;

    auto load_stage = [&](int s) {
        int k0 = s << 5;
        uint32_t stb = uS + (uint32_t)(s & 1) * 32768;
#pragma unroll
        for (int i = 0; i < 2; i++) {
            int chunk = t + i * 256;
            int r = chunk >> 2, c = chunk & 3;
            uint32_t so = SWZ64((uint32_t)(r * 64 + c * 16));
            size_t goA = (size_t)(m0 + r) * K + k0 + c * 8;
            size_t goB = (size_t)(n0 + r) * K + k0 + c * 8;
            cpasync16(stb + so,          Ah + goA);
            cpasync16(stb + 8192  + so,  Al + goA);
            cpasync16(stb + 16384 + so,  Bh + goB);
            cpasync16(stb + 24576 + so,  Bl + goB);
        }
        asm volatile("cp.async.commit_group;" ::: "memory");
    };

    load_stage(0);
    for (int s = 0; s < nk; s++) {
        if (s + 1 < nk) {
            load_stage(s + 1);
            asm volatile("cp.async.wait_group 1;" ::: "memory");
        } else {
            asm volatile("cp.async.wait_group 0;" ::: "memory");
        }
        __syncthreads();
        uint32_t stb = uS + (uint32_t)(s & 1) * 32768;
        uint32_t uAh = stb, uAl = stb + 8192, uBh = stb + 16384, uBl = stb + 24576;
#pragma unroll
        for (int kk = 0; kk < 2; kk++) {
            uint32_t kb = (uint32_t)kk * 32 + fb;
            uint32_t ah0[4], ah1[4], al0[4], al1[4];
            {
                uint32_t r0o = (uint32_t)(wm*32 + fr) * 64 + kb;
                uint32_t r1o = (uint32_t)(wm*32 + 16 + fr) * 64 + kb;
                ldm4(ah0, uAh + SWZ64(r0o));
                ldm4(ah1, uAh + SWZ64(r1o));
                ldm4(al0, uAl + SWZ64(r0o));
                ldm4(al1, uAl + SWZ64(r1o));
            }
#pragma unroll
            for (int np = 0; np < 4; np++) {
                uint32_t bh[4], bl[4];
                uint32_t rno = (uint32_t)(wn*64 + np*16 + fr) * 64 + kb;
                ldm4(bh, uBh + SWZ64(rno));
                ldm4(bl, uBl + SWZ64(rno));
                mma_bf16(acc[0][np*2],   ah0, bh[0], bh[2]);
                mma_bf16(acc[1][np*2],   ah1, bh[0], bh[2]);
                mma_bf16(acc[0][np*2+1], ah0, bh[1], bh[3]);
                mma_bf16(acc[1][np*2+1], ah1, bh[1], bh[3]);
                mma_bf16(acc[0][np*2],   ah0, bl[0], bl[2]);
                mma_bf16(acc[1][np*2],   ah1, bl[0], bl[2]);
                mma_bf16(acc[0][np*2+1], ah0, bl[1], bl[3]);
                mma_bf16(acc[1][np*2+1], ah1, bl[1], bl[3]);
                mma_bf16(acc[0][np*2],   al0, bh[0], bh[2]);
                mma_bf16(acc[1][np*2],   al1, bh[0], bh[2]);
                mma_bf16(acc[0][np*2+1], al0, bh[1], bh[3]);
                mma_bf16(acc[1][np*2+1], al1, bh[1], bh[3]);
            }
        }
        __syncthreads();
    }

    int qrow = lane >> 2, qcol = (lane & 3) * 2;
#pragma unroll
    for (int m = 0; m < 2; m++) {
        int row0 = m0 + wm*32 + m*16 + qrow;
#pragma unroll
        for (int nt = 0; nt < 8; nt++) {
            int col = n0 + wn*64 + nt*8 + qcol;
            float b0 = bias ? bias[col] : 0.f;
            float b1 = bias ? bias[col+1] : 0.f;
            float2 v0 = make_float2(acc[m][nt][0] + b0, acc[m][nt][1] + b1);
            float2 v1 = make_float2(acc[m][nt][2] + b0, acc[m][nt][3] + b1);
            *(float2*)(C + (size_t)row0 * N + col) = v0;
            *(float2*)(C + (size_t)(row0 + 8) * N + col) = v1;
        }
    }
}

// ---------------- weight prep ----------------
__global__ void wprep_t_kernel(const float* __restrict__ W, __nv_bfloat16* __restrict__ Th,
                               __nv_bfloat16* __restrict__ Tl, int K, int N) {
    __shared__ float tile[32][33];
    int k0 = blockIdx.x * 32, n0 = blockIdx.y * 32;
    int tx = threadIdx.x, ty = threadIdx.y;
    for (int j = 0; j < 32; j += 8)
        tile[ty + j][tx] = W[(size_t)(k0 + ty + j) * N + n0 + tx];
    __syncthreads();
    for (int j = 0; j < 32; j += 8) {
        float v = tile[tx][ty + j];
        size_t o = (size_t)(n0 + ty + j) * K + k0 + tx;
        __nv_bfloat16 h, l; bf16split(v, &h, &l);
        Th[o] = h; Tl[o] = l;
    }
}
__global__ void wprep_kernel(const float* __restrict__ W, __nv_bfloat16* __restrict__ H,
                             __nv_bfloat16* __restrict__ L, int n) {
    int i = blockIdx.x * 256 + threadIdx.x;
    if (i < n) { __nv_bfloat16 h, l; bf16split(W[i], &h, &l); H[i] = h; L[i] = l; }
}

// ---------------- layernorm -> bf16 split ----------------
__global__ void ln_kernel(const float* __restrict__ x, const float* __restrict__ g,
                          const float* __restrict__ bta) {
    int row = blockIdx.x;
    const float* xr = x + (size_t)row * DIM;
    int t = threadIdx.x;
    float v[4]; float s = 0.f;
#pragma unroll
    for (int i = 0; i < 4; i++) { v[i] = xr[t + 256*i]; s += v[i]; }
    __shared__ float red[256];
    red[t] = s; __syncthreads();
    for (int k = 128; k > 0; k >>= 1) { if (t < k) red[t] += red[t+k]; __syncthreads(); }
    float mu = red[0] * (1.0f/DIM); __syncthreads();
    float s2 = 0.f;
#pragma unroll
    for (int i = 0; i < 4; i++) { float d = v[i]-mu; s2 += d*d; }
    red[t] = s2; __syncthreads();
    for (int k = 128; k > 0; k >>= 1) { if (t < k) red[t] += red[t+k]; __syncthreads(); }
    float inv = 1.0f / sqrtf(red[0] * (1.0f/DIM) + 1e-5f);
#pragma unroll
    for (int i = 0; i < 4; i++) {
        int d = t + 256*i;
        float y = (v[i]-mu)*inv*g[d] + bta[d];
        __nv_bfloat16 h, l; bf16split(y, &h, &l);
        g_xnh[(size_t)row*DIM + d] = h;
        g_xnl[(size_t)row*DIM + d] = l;
    }
}

// ---------------- light attention: 3x64 chunks, online softmax, 4x4 reg blocking ----------------
__global__ __launch_bounds__(256) void light_attn_kernel() {
    extern __shared__ float lsm[];
    float* sq = lsm;
    float* sk = sq + 64*65;
    float* sv = sk + 64*65;
    float* sp = sv + 64*65;
    int win = blockIdx.x, h = blockIdx.y, b = blockIdx.z;
    int t = threadIdx.x;
    for (int e = t; e < 64*64; e += 256) {
        int i = e >> 6, d = e & 63;
        int n = win*64 + i;
        sq[i*65 + d] = g_qkv[((size_t)(b*SEQ + n))*QKVD + h*64 + d] * 0.125f;
    }
    int qg = t >> 4, kg = t & 15;
    float m[4], l[4], acc[4][4];
#pragma unroll
    for (int u = 0; u < 4; u++) {
        m[u] = -FLT_MAX; l[u] = 0.f;
#pragma unroll
        for (int w = 0; w < 4; w++) acc[u][w] = 0.f;
    }

    for (int c = 0; c < 3; c++) {
        int nbase = (win - 1 + c) * 64;
        __syncthreads();
        for (int e = t; e < 64*64; e += 256) {
            int j = e >> 6, d = e & 63;
            int n = nbase + j;
            bool ok = (n >= 0 && n < SEQ);
            size_t base = ((size_t)(b*SEQ + n))*QKVD + h*64 + d;
            sk[j*65 + d] = ok ? g_qkv[base + 512]  : 0.f;
            sv[j*65 + d] = ok ? g_qkv[base + 1024] : 0.f;
        }
        __syncthreads();
        float s[4][4];
#pragma unroll
        for (int u = 0; u < 4; u++)
#pragma unroll
            for (int w = 0; w < 4; w++) s[u][w] = 0.f;
        for (int d = 0; d < 64; d++) {
            float qv[4], kv[4];
#pragma unroll
            for (int u = 0; u < 4; u++) qv[u] = sq[(qg + 16*u)*65 + d];
#pragma unroll
            for (int w = 0; w < 4; w++) kv[w] = sk[(kg + 16*w)*65 + d];
#pragma unroll
            for (int u = 0; u < 4; u++)
#pragma unroll
                for (int w = 0; w < 4; w++) s[u][w] = fmaf(qv[u], kv[w], s[u][w]);
        }
#pragma unroll
        for (int u = 0; u < 4; u++) {
            int iabs = win*64 + qg + 16*u;
            float cm = -FLT_MAX;
#pragma unroll
            for (int w = 0; w < 4; w++) {
                int jabs = nbase + kg + 16*w;
                bool valid = (jabs >= 0) && (jabs < SEQ) && (abs(iabs - jabs) <= WIN);
                float sx = valid ? s[u][w] : -FLT_MAX;
                s[u][w] = sx;
                cm = fmaxf(cm, sx);
            }
#pragma unroll
            for (int off = 1; off < 16; off <<= 1)
                cm = fmaxf(cm, __shfl_xor_sync(0xFFFFFFFFu, cm, off));
            float mn = fmaxf(m[u], cm);
            float scale = expf(m[u] - mn);
            bool anyvalid = (mn != -FLT_MAX);
            float ls = 0.f;
#pragma unroll
            for (int w = 0; w < 4; w++) {
                float p = anyvalid ? expf(s[u][w] - mn) : 0.f;
                sp[(qg + 16*u)*65 + kg + 16*w] = p;
                ls += p;
            }
#pragma unroll
            for (int off = 1; off < 16; off <<= 1)
                ls += __shfl_xor_sync(0xFFFFFFFFu, ls, off);
            l[u] = l[u]*scale + ls;
            m[u] = mn;
#pragma unroll
            for (int w = 0; w < 4; w++) acc[u][w] *= scale;
        }
        __syncwarp();
        for (int k = 0; k < 64; k++) {
            float pv[4], vv[4];
#pragma unroll
            for (int u = 0; u < 4; u++) pv[u] = sp[(qg + 16*u)*65 + k];
#pragma unroll
            for (int w = 0; w < 4; w++) vv[w] = sv[k*65 + kg + 16*w];
#pragma unroll
            for (int u = 0; u < 4; u++)
#pragma unroll
                for (int w = 0; w < 4; w++) acc[u][w] = fmaf(pv[u], vv[w], acc[u][w]);
        }
        __syncwarp();
    }
#pragma unroll
    for (int u = 0; u < 4; u++) {
        float invl = 1.0f / l[u];
        int iabs = win*64 + qg + 16*u;
#pragma unroll
        for (int w = 0; w < 4; w++) {
            float y = acc[u][w] * invl;
            size_t o = ((size_t)(b*SEQ + iabs))*HDIM + h*64 + kg + 16*w;
            __nv_bfloat16 hh, ll; bf16split(y, &hh, &ll);
            g_lah[o] = hh; g_lal[o] = ll;
        }
    }
}

// ---------------- routing scores ----------------
__global__ void route_score_kernel(const float* __restrict__ x,
                                   const float* __restrict__ qt,
                                   const float* __restrict__ kt) {
    int row = blockIdx.x;
    int t = threadIdx.x;
    const float* xr = x + (size_t)row * DIM;
    float sq = 0.f, sk = 0.f;
#pragma unroll
    for (int i = t; i < DIM; i += 256) {
        float v = xr[i];
        sq = fmaf(v, qt[i], sq);
        sk = fmaf(v, kt[i], sk);
    }
    __shared__ float r1[256], r2[256];
    r1[t] = sq; r2[t] = sk; __syncthreads();
    for (int k = 128; k > 0; k >>= 1) {
        if (t < k) { r1[t] += r1[t+k]; r2[t] += r2[t+k]; }
        __syncthreads();
    }
    if (t == 0) { g_sq[row] = r1[0]; g_skv[row] = r2[0]; }
}

// ---------------- coordinate descent + exact top-k (bitonic) ----------------
__global__ __launch_bounds__(1024) void route_select_kernel() {
    extern __shared__ unsigned char rsm[];
    unsigned long long* key = (unsigned long long*)rsm;
    float* s  = (float*)(key + SEQ);
    float* bb = s + SEQ;
    __shared__ float red[1024];
    int b = blockIdx.x, which = blockIdx.y;
    int t = threadIdx.x;
    const float* src = which ? g_skv : g_sq;
    for (int i = t; i < SEQ; i += 1024) { float v = src[b*SEQ + i]; s[i] = v; bb[i] = -v; }
    __syncthreads();
    float cur = 4.0f;
    const float logk = logf(1152.0f);
    float a = 0.f;
    for (int it = 0; it < 20; it++) {
        float m = -FLT_MAX;
        for (int i = t; i < SEQ; i += 1024) m = fmaxf(m, (s[i] + bb[i]) / cur);
        red[t] = m; __syncthreads();
        for (int k = 512; k > 0; k >>= 1) { if (t < k) red[t] = fmaxf(red[t], red[t+k]); __syncthreads(); }
        m = red[0]; __syncthreads();
        float sum = 0.f;
        for (int i = t; i < SEQ; i += 1024) sum += expf((s[i] + bb[i]) / cur - m);
        red[t] = sum; __syncthreads();
        for (int k = 512; k > 0; k >>= 1) { if (t < k) red[t] += red[t+k]; __syncthreads(); }
        float lse = m + logf(red[0]);
        a = cur * (logk - lse);
        __syncthreads();
        for (int i = t; i < SEQ; i += 1024) bb[i] = -fmaxf(s[i] + a, 0.f);
        cur = fmaxf(cur * 0.7f, 0.03f);
        __syncthreads();
    }
    for (int i = t; i < SEQ; i += 1024) {
        float ta = s[i] + a;
        float sc = expf((ta + bb[i]) / cur);
        unsigned int sb = __float_as_uint(sc);
        key[i] = ((unsigned long long)sb << 32)
               | (unsigned long long)(0xFFFFFFFFu - (unsigned)i);
    }
    __syncthreads();
    for (int size = 2; size <= SEQ; size <<= 1) {
        for (int stride = size >> 1; stride > 0; stride >>= 1) {
            for (int i = t; i < SEQ; i += 1024) {
                int j = i ^ stride;
                if (j > i) {
                    bool desc = ((i & size) == 0);
                    unsigned long long ki = key[i], kj = key[j];
                    if ((ki < kj) == desc) { key[i] = kj; key[j] = ki; }
                }
            }
            __syncthreads();
        }
    }
    if (t < NSEL) {
        unsigned idxv = 0xFFFFFFFFu - (unsigned)(key[t] & 0xFFFFFFFFull);
        g_idx[(which*BATCH + b)*NSEL + t] = (int)idxv;
    }
}

// ---------------- gather routed + rmsnorm -> bf16 split ----------------
__global__ void gather_rms_kernel(const float* __restrict__ x,
                                  const float* __restrict__ gamma) {
    int j = blockIdx.x, b = blockIdx.y, which = blockIdx.z;
    int idx = g_idx[(which*BATCH + b)*NSEL + j];
    const float* xr = x + ((size_t)b*SEQ + idx)*DIM;
    int t = threadIdx.x;
    float v[4]; float ss = 0.f;
#pragma unroll
    for (int i = 0; i < 4; i++) { v[i] = xr[t + 256*i]; ss += v[i]*v[i]; }
    __shared__ float red[256];
    red[t] = ss; __syncthreads();
    for (int k = 128; k > 0; k >>= 1) { if (t < k) red[t] += red[t+k]; __syncthreads(); }
    float nrm = sqrtf(red[0]);
    float scale = 32.0f / fmaxf(nrm, 1e-12f);
    size_t base = (((size_t)which*BATCH + b)*NSEL + j)*DIM;
#pragma unroll
    for (int i = 0; i < 4; i++) {
        int d = t + 256*i;
        float y = v[i]*scale*gamma[d];
        __nv_bfloat16 h, l; bf16split(y, &h, &l);
        g_rth[base + d] = h; g_rtl[base + d] = l;
    }
}

// ---------------- rope on heavy q ----------------
__global__ void rope_q_kernel() {
    int e = blockIdx.x*256 + threadIdx.x;
    int d = e & 31;
    int h = (e >> 5) & 7;
    int j = (e >> 8) & 1023;
    int b = e >> 18;
    int tpos = g_idx[b*NSEL + j];
    float invf = powf(10000.0f, -(float)d / 32.0f);
    float th = (float)tpos * invf;
    float c, sn; sincosf(th, &sn, &c);
    size_t base = ((size_t)(b*NSEL + j))*HDIM + h*DHEAD;
    float x1 = g_qh[base + d], x2 = g_qh[base + d + 32];
    g_qh[base + d]      = x1*c - x2*sn;
    g_qh[base + d + 32] = x2*c + x1*sn;
}

// ---------------- pack k/v with rope + null kv ----------------
__global__ void pack_kv_kernel(const float* __restrict__ null_kv) {
    int e = blockIdx.x*256 + threadIdx.x;
    if (e >= BATCH*HEADS*KVLEN*32) return;
    int d  = e & 31;
    int jj = (e >> 5) % KVLEN;
    int hb = (e >> 5) / KVLEN;
    int h = hb & 7, b = hb >> 3;
    size_t obase = ((size_t)(b*HEADS + h)*KVLEN + jj)*DHEAD;
    if (jj == 0) {
        g_k[obase + d]      = null_kv[h*DHEAD + d];
        g_k[obase + d + 32] = null_kv[h*DHEAD + d + 32];
        g_v[obase + d]      = null_kv[HEADS*DHEAD + h*DHEAD + d];
        g_v[obase + d + 32] = null_kv[HEADS*DHEAD + h*DHEAD + d + 32];
    } else {
        int j = jj - 1;
        int tpos = g_idx[(BATCH + b)*NSEL + j];
        size_t ibase = ((size_t)(b*NSEL + j))*DIM + h*128;
        float k1 = g_kv[ibase + d], k2 = g_kv[ibase + d + 32];
        float invf = powf(10000.0f, -(float)d / 32.0f);
        float th = (float)tpos * invf;
        float c, sn; sincosf(th, &sn, &c);
        g_k[obase + d]      = k1*c - k2*sn;
        g_k[obase + d + 32] = k2*c + k1*sn;
        g_v[obase + d]      = g_kv[ibase + 64 + d];
        g_v[obase + d + 32] = g_kv[ibase + 64 + d + 32];
    }
}

// ---------------- heavy attention: 64-key chunks, 4x4 reg blocking ----------------
__global__ __launch_bounds__(256) void heavy_attn_kernel() {
    extern __shared__ float hsm[];
    float* sq = hsm;
    float* sk = sq + 64*65;
    float* sv = sk + 64*65;
    float* sp = sv + 64*65;
    int qt = blockIdx.x, h = blockIdx.y, b = blockIdx.z;
    int t = threadIdx.x;
    for (int e = t; e < 64*64; e += 256) {
        int i = e >> 6, d = e & 63;
        sq[i*65 + d] = g_qh[((size_t)(b*NSEL + qt*64 + i))*HDIM + h*64 + d] * 0.125f;
    }
    int qg = t >> 4, kg = t & 15;
    float m[4], l[4], acc[4][4];
#pragma unroll
    for (int u = 0; u < 4; u++) {
        m[u] = -FLT_MAX; l[u] = 0.f;
#pragma unroll
        for (int w = 0; w < 4; w++) acc[u][w] = 0.f;
    }
    size_t kvbase = ((size_t)(b*HEADS + h))*KVLEN*DHEAD;
    for (int c0 = 0; c0 < KVLEN; c0 += 64) {
        int cnt = min(64, KVLEN - c0);
        __syncthreads();
        for (int e = t; e < 64*64; e += 256) {
            int j = e >> 6, d = e & 63;
            bool ok = j < cnt;
            sk[j*65 + d] = ok ? g_k[kvbase + (size_t)(c0 + j)*DHEAD + d] : 0.f;
            sv[j*65 + d] = ok ? g_v[kvbase + (size_t)(c0 + j)*DHEAD + d] : 0.f;
        }
        __syncthreads();
        float s[4][4];
#pragma unroll
        for (int u = 0; u < 4; u++)
#pragma unroll
            for (int w = 0; w < 4; w++) s[u][w] = 0.f;
        for (int d = 0; d < 64; d++) {
            float qv[4], kv[4];
#pragma unroll
            for (int u = 0; u < 4; u++) qv[u] = sq[(qg + 16*u)*65 + d];
#pragma unroll
            for (int w = 0; w < 4; w++) kv[w] = sk[(kg + 16*w)*65 + d];
#pragma unroll
            for (int u = 0; u < 4; u++)
#pragma unroll
                for (int w = 0; w < 4; w++) s[u][w] = fmaf(qv[u], kv[w], s[u][w]);
        }
#pragma unroll
        for (int u = 0; u < 4; u++) {
            float cm = -FLT_MAX;
#pragma unroll
            for (int w = 0; w < 4; w++) {
                float sx = (kg + 16*w < cnt) ? s[u][w] : -FLT_MAX;
                s[u][w] = sx;
                cm = fmaxf(cm, sx);
            }
#pragma unroll
            for (int off = 1; off < 16; off <<= 1)
                cm = fmaxf(cm, __shfl_xor_sync(0xFFFFFFFFu, cm, off));
            float mn = fmaxf(m[u], cm);
            float scale = expf(m[u] - mn);
            float ls = 0.f;
#pragma unroll
            for (int w = 0; w < 4; w++) {
                float p = expf(s[u][w] - mn);
                sp[(qg + 16*u)*65 + kg + 16*w] = p;
                ls += p;
            }
#pragma unroll
            for (int off = 1; off < 16; off <<= 1)
                ls += __shfl_xor_sync(0xFFFFFFFFu, ls, off);
            l[u] = l[u]*scale + ls;
            m[u] = mn;
#pragma unroll
            for (int w = 0; w < 4; w++) acc[u][w] *= scale;
        }
        __syncwarp();
        for (int k = 0; k < 64; k++) {
            float pv[4], vv[4];
#pragma unroll
            for (int u = 0; u < 4; u++) pv[u] = sp[(qg + 16*u)*65 + k];
#pragma unroll
            for (int w = 0; w < 4; w++) vv[w] = sv[k*65 + kg + 16*w];
#pragma unroll
            for (int u = 0; u < 4; u++)
#pragma unroll
                for (int w = 0; w < 4; w++) acc[u][w] = fmaf(pv[u], vv[w], acc[u][w]);
        }
        __syncwarp();
    }
#pragma unroll
    for (int u = 0; u < 4; u++) {
        float invl = 1.0f / l[u];
#pragma unroll
        for (int w = 0; w < 4; w++) {
            float y = acc[u][w] * invl;
            size_t o = ((size_t)(b*NSEL + qt*64 + qg + 16*u))*HDIM + h*64 + kg + 16*w;
            __nv_bfloat16 hh, ll; bf16split(y, &hh, &ll);
            g_hah[o] = hh; g_hal[o] = ll;
        }
    }
}

// ---------------- scatter ----------------
__global__ void scatter_kernel(float* __restrict__ out, const float* __restrict__ nullq) {
    int j = blockIdx.x & 1023, b = blockIdx.x >> 10;
    int i = g_idx[b*NSEL + j];
    float* orow = out + ((size_t)b*SEQ + i)*DIM;
    const float* hrow = g_ho + ((size_t)(b*NSEL + j))*DIM;
    for (int d = threadIdx.x; d < DIM; d += 256)
        orow[d] += hrow[d] - nullq[d];
}

// ---------------- launch ----------------
extern "C" void kernel_launch(void* const* d_in, const int* in_sizes, int n_in,
                              void* d_out, int out_size) {
    const float* x       = (const float*)d_in[0];
    const float* ln_g    = (const float*)d_in[1];
    const float* ln_b    = (const float*)d_in[2];
    const float* qkv_w   = (const float*)d_in[3];
    const float* lout_w  = (const float*)d_in[4];
    const float* q_tok   = (const float*)d_in[5];
    const float* kv_tok  = (const float*)d_in[6];
    const float* hgamma  = (const float*)d_in[7];
    const float* hq_w    = (const float*)d_in[8];
    const float* hkv_w   = (const float*)d_in[9];
    const float* hnullkv = (const float*)d_in[10];
    const float* hout_w  = (const float*)d_in[11];
    const float* nullq   = (const float*)d_in[12];
    float* out = (float*)d_out;

    static cudaStream_t s2 = nullptr;
    static cudaEvent_t evFork = nullptr, evJoin = nullptr;
    if (!s2) {
        cudaStreamCreateWithFlags(&s2, cudaStreamNonBlocking);
        cudaEventCreateWithFlags(&evFork, cudaEventDisableTiming);
        cudaEventCreateWithFlags(&evJoin, cudaEventDisableTiming);
    }

    float *p_qkv, *p_qh, *p_kv, *p_ho;
    __nv_bfloat16 *p_xnh, *p_xnl, *p_lah, *p_lal, *p_rth, *p_rtl, *p_hah, *p_hal;
    __nv_bfloat16 *p_wqh, *p_wql, *p_wlh, *p_wll, *p_whqh, *p_whql, *p_wkh, *p_wkl, *p_woh, *p_wol;
    cudaGetSymbolAddress((void**)&p_qkv, g_qkv);
    cudaGetSymbolAddress((void**)&p_qh, g_qh);
    cudaGetSymbolAddress((void**)&p_kv, g_kv);
    cudaGetSymbolAddress((void**)&p_ho, g_ho);
    cudaGetSymbolAddress((void**)&p_xnh, g_xnh); cudaGetSymbolAddress((void**)&p_xnl, g_xnl);
    cudaGetSymbolAddress((void**)&p_lah, g_lah); cudaGetSymbolAddress((void**)&p_lal, g_lal);
    cudaGetSymbolAddress((void**)&p_rth, g_rth); cudaGetSymbolAddress((void**)&p_rtl, g_rtl);
    cudaGetSymbolAddress((void**)&p_hah, g_hah); cudaGetSymbolAddress((void**)&p_hal, g_hal);
    cudaGetSymbolAddress((void**)&p_wqh, w_qkvh); cudaGetSymbolAddress((void**)&p_wql, w_qkvl);
    cudaGetSymbolAddress((void**)&p_wlh, w_louth); cudaGetSymbolAddress((void**)&p_wll, w_loutl);
    cudaGetSymbolAddress((void**)&p_whqh, w_hqh); cudaGetSymbolAddress((void**)&p_whql, w_hql);
    cudaGetSymbolAddress((void**)&p_wkh, w_hkvh); cudaGetSymbolAddress((void**)&p_wkl, w_hkvl);
    cudaGetSymbolAddress((void**)&p_woh, w_houth); cudaGetSymbolAddress((void**)&p_wol, w_houtl);

    const int LSMEM = 4*64*65*4;
    const int HSMEM = 4*64*65*4;
    const int RSMEM = SEQ*8 + 2*SEQ*4;
    const int GSMEM = 65536 + 1024;
    cudaFuncSetAttribute(light_attn_kernel,  cudaFuncAttributeMaxDynamicSharedMemorySize, LSMEM);
    cudaFuncSetAttribute(heavy_attn_kernel,  cudaFuncAttributeMaxDynamicSharedMemorySize, HSMEM);
    cudaFuncSetAttribute(route_select_kernel, cudaFuncAttributeMaxDynamicSharedMemorySize, RSMEM);
    cudaFuncSetAttribute(bmm_kernel, cudaFuncAttributeMaxDynamicSharedMemorySize, GSMEM);

    cudaEventRecord(evFork, 0);
    cudaStreamWaitEvent(s2, evFork, 0);

    // ======== stream 0: light path ========
    wprep_t_kernel<<<dim3(DIM/32, QKVD/32), dim3(32,8)>>>(qkv_w, p_wqh, p_wql, DIM, QKVD);
    ln_kernel<<<BATCH*SEQ, 256>>>(x, ln_g, ln_b);
    bmm_kernel<<<dim3(QKVD/128, (BATCH*SEQ)/128), 256, GSMEM>>>(
        p_xnh, p_xnl, p_wqh, p_wql, p_qkv, BATCH*SEQ, QKVD, DIM, nullptr);
    light_attn_kernel<<<dim3(NWIN, HEADS, BATCH), 256, LSMEM>>>();
    wprep_t_kernel<<<dim3(HDIM/32, DIM/32), dim3(32,8)>>>(lout_w, p_wlh, p_wll, HDIM, DIM);
    bmm_kernel<<<dim3(DIM/128, (BATCH*SEQ)/128), 256, GSMEM>>>(
        p_lah, p_lal, p_wlh, p_wll, out, BATCH*SEQ, DIM, HDIM, nullq);

    // ======== stream s2: routing + heavy path ========
    wprep_kernel<<<(DIM*DIM + 255)/256, 256, 0, s2>>>(hkv_w, p_wkh, p_wkl, DIM*DIM);
    wprep_t_kernel<<<dim3(DIM/32, HDIM/32), dim3(32,8), 0, s2>>>(hq_w, p_whqh, p_whql, DIM, HDIM);
    wprep_t_kernel<<<dim3(HDIM/32, DIM/32), dim3(32,8), 0, s2>>>(hout_w, p_woh, p_wol, HDIM, DIM);
    route_score_kernel<<<BATCH*SEQ, 256, 0, s2>>>(x, q_tok, kv_tok);
    route_select_kernel<<<dim3(BATCH, 2), 1024, RSMEM, s2>>>();
    gather_rms_kernel<<<dim3(NSEL, BATCH, 2), 256, 0, s2>>>(x, hgamma);
    bmm_kernel<<<dim3(HDIM/128, (BATCH*NSEL)/128), 256, GSMEM, s2>>>(
        p_rth, p_rtl, p_whqh, p_whql, p_qh, BATCH*NSEL, HDIM, DIM, nullptr);
    rope_q_kernel<<<(BATCH*NSEL*HEADS*32)/256, 256, 0, s2>>>();
    bmm_kernel<<<dim3(DIM/128, (BATCH*NSEL)/128), 256, GSMEM, s2>>>(
        p_rth + (size_t)BATCH*NSEL*DIM, p_rtl + (size_t)BATCH*NSEL*DIM,
        p_wkh, p_wkl, p_kv, BATCH*NSEL, DIM, DIM, nullptr);
    pack_kv_kernel<<<(BATCH*HEADS*KVLEN*32 + 255)/256, 256, 0, s2>>>(hnullkv);
    heavy_attn_kernel<<<dim3(16, HEADS, BATCH), 256, HSMEM, s2>>>();
    bmm_kernel<<<dim3(DIM/128, (BATCH*NSEL)/128), 256, GSMEM, s2>>>(
        p_hah, p_hal, p_woh, p_wol, p_ho, BATCH*NSEL, DIM, HDIM, nullptr);

    cudaEventRecord(evJoin, s2);
    cudaStreamWaitEvent(0, evJoin, 0);
    scatter_kernel<<<BATCH*NSEL, 256>>>(out, nullq);
}

// round 16
// speedup vs baseline: 1.2194x; 1.0629x over previous
// R16: resubmission of R15 (broker infra failure, no kernel signal). float4-LDS attention + __expf.
#include <cuda_runtime.h>
#include <cuda_bf16.h>
#include <math.h>
#include <float.h>
#include <stdint.h>

#define BATCH 2
#define SEQ   8192
#define DIM   1024
#define HEADS 8
#define DHEAD 64
#define HDIM  512
#define QKVD  1536
#define WIN   64
#define NWIN  128
#define NSEL  1024
#define KVLEN 1025
#define AP    68     // attention smem row pitch (floats), 16B aligned, 4-bank skew

// ---------------- scratch ----------------
__device__ float g_qkv[(size_t)BATCH*SEQ*QKVD];
__device__ float g_sq[BATCH*SEQ];
__device__ float g_skv[BATCH*SEQ];
__device__ int   g_idx[2*BATCH*NSEL];
__device__ float g_qh[(size_t)BATCH*NSEL*HDIM];
__device__ float g_kv[(size_t)BATCH*NSEL*DIM];
__device__ float g_k[(size_t)BATCH*HEADS*KVLEN*DHEAD];
__device__ float g_v[(size_t)BATCH*HEADS*KVLEN*DHEAD];
__device__ float g_ho[(size_t)BATCH*NSEL*DIM];
// bf16 split activations
__device__ __nv_bfloat16 g_xnh[(size_t)BATCH*SEQ*DIM],  g_xnl[(size_t)BATCH*SEQ*DIM];
__device__ __nv_bfloat16 g_lah[(size_t)BATCH*SEQ*HDIM], g_lal[(size_t)BATCH*SEQ*HDIM];
__device__ __nv_bfloat16 g_rth[(size_t)2*BATCH*NSEL*DIM], g_rtl[(size_t)2*BATCH*NSEL*DIM];
__device__ __nv_bfloat16 g_hah[(size_t)BATCH*NSEL*HDIM], g_hal[(size_t)BATCH*NSEL*HDIM];
// bf16 split weights, stored [N][K] (B^T)
__device__ __nv_bfloat16 w_qkvh[(size_t)QKVD*DIM], w_qkvl[(size_t)QKVD*DIM];
__device__ __nv_bfloat16 w_louth[(size_t)DIM*HDIM], w_loutl[(size_t)DIM*HDIM];
__device__ __nv_bfloat16 w_hqh[(size_t)HDIM*DIM],  w_hql[(size_t)HDIM*DIM];
__device__ __nv_bfloat16 w_hkvh[(size_t)DIM*DIM],  w_hkvl[(size_t)DIM*DIM];
__device__ __nv_bfloat16 w_houth[(size_t)DIM*HDIM], w_houtl[(size_t)DIM*HDIM];

// ---------------- helpers ----------------
__device__ __forceinline__ uint32_t smem_u32(const void* p) {
    uint32_t a;
    asm("{ .reg .u64 t; cvta.to.shared.u64 t, %1; cvt.u32.u64 %0, t; }" : "=r"(a) : "l"(p));
    return a;
}
#define SWZ64(o)  ((o) ^ (((o) >> 3) & 0x30))

__device__ __forceinline__ void ldm4(uint32_t* r, uint32_t addr) {
    asm volatile("ldmatrix.sync.aligned.m8n8.x4.shared.b16 {%0,%1,%2,%3}, [%4];"
        : "=r"(r[0]), "=r"(r[1]), "=r"(r[2]), "=r"(r[3]) : "r"(addr));
}
__device__ __forceinline__ void mma_bf16(float* d, const uint32_t* a, uint32_t b0, uint32_t b1) {
    asm volatile("mma.sync.aligned.m16n8k16.row.col.f32.bf16.bf16.f32 "
        "{%0,%1,%2,%3}, {%4,%5,%6,%7}, {%8,%9}, {%0,%1,%2,%3};"
        : "+f"(d[0]), "+f"(d[1]), "+f"(d[2]), "+f"(d[3])
        : "r"(a[0]), "r"(a[1]), "r"(a[2]), "r"(a[3]), "r"(b0), "r"(b1));
}
__device__ __forceinline__ void cpasync16(uint32_t dst, const void* src) {
    asm volatile("cp.async.cg.shared.global [%0], [%1], 16;" :: "r"(dst), "l"(src));
}
__device__ __forceinline__ void bf16split(float v, __nv_bfloat16* hi, __nv_bfloat16* lo) {
    __nv_bfloat16 h = __float2bfloat16(v);
    *hi = h;
    *lo = __float2bfloat16(v - __bfloat162float(h));
}

// ---------------- pipelined mma.sync split-bf16 GEMM: 128x128 tile, warp 32x64 ----------------
__global__ __launch_bounds__(256, 2) void bmm_kernel(
        const __nv_bfloat16* __restrict__ Ah, const __nv_bfloat16* __restrict__ Al,
        const __nv_bfloat16* __restrict__ Bh, const __nv_bfloat16* __restrict__ Bl,
        float* __restrict__ C, int M, int N, int K, const float* __restrict__ bias) {
    extern __shared__ unsigned char dsm_raw[];
    unsigned char* sb = (unsigned char*)(((uintptr_t)dsm_raw + 1023) & ~(uintptr_t)1023);
    int t = threadIdx.x, wid = t >> 5, lane = t & 31;
    int n0 = blockIdx.x * 128, m0 = blockIdx.y * 128;
    uint32_t uS = smem_u32(sb);
    int wm = wid & 3, wn = wid >> 2;

    float acc[2][8][4];
#pragma unroll
    for (int m = 0; m < 2; m++)
#pragma unroll
        for (int n = 0; n < 8; n++)
#pragma unroll
            for (int q = 0; q < 4; q++) acc[m][n][q] = 0.f;

    int fr = lane & 15;
    uint32_t fb = (uint32_t)(lane >> 4) * 16;
    int nk = K >> 5;

    auto load_stage = [&](int s) {
        int k0 = s << 5;
        uint32_t stb = uS + (uint32_t)(s & 1) * 32768;
#pragma unroll
        for (int i = 0; i < 2; i++) {
            int chunk = t + i * 256;
            int r = chunk >> 2, c = chunk & 3;
            uint32_t so = SWZ64((uint32_t)(r * 64 + c * 16));
            size_t goA = (size_t)(m0 + r) * K + k0 + c * 8;
            size_t goB = (size_t)(n0 + r) * K + k0 + c * 8;
            cpasync16(stb + so,          Ah + goA);
            cpasync16(stb + 8192  + so,  Al + goA);
            cpasync16(stb + 16384 + so,  Bh + goB);
            cpasync16(stb + 24576 + so,  Bl + goB);
        }
        asm volatile("cp.async.commit_group;" ::: "memory");
    };

    load_stage(0);
    for (int s = 0; s < nk; s++) {
        if (s + 1 < nk) {
            load_stage(s + 1);
            asm volatile("cp.async.wait_group 1;" ::: "memory");
        } else {
            asm volatile("cp.async.wait_group 0;" ::: "memory");
        }
        __syncthreads();
        uint32_t stb = uS + (uint32_t)(s & 1) * 32768;
        uint32_t uAh = stb, uAl = stb + 8192, uBh = stb + 16384, uBl = stb + 24576;
#pragma unroll
        for (int kk = 0; kk < 2; kk++) {
            uint32_t kb = (uint32_t)kk * 32 + fb;
            uint32_t ah0[4], ah1[4], al0[4], al1[4];
            {
                uint32_t r0o = (uint32_t)(wm*32 + fr) * 64 + kb;
                uint32_t r1o = (uint32_t)(wm*32 + 16 + fr) * 64 + kb;
                ldm4(ah0, uAh + SWZ64(r0o));
                ldm4(ah1, uAh + SWZ64(r1o));
                ldm4(al0, uAl + SWZ64(r0o));
                ldm4(al1, uAl + SWZ64(r1o));
            }
#pragma unroll
            for (int np = 0; np < 4; np++) {
                uint32_t bh[4], bl[4];
                uint32_t rno = (uint32_t)(wn*64 + np*16 + fr) * 64 + kb;
                ldm4(bh, uBh + SWZ64(rno));
                ldm4(bl, uBl + SWZ64(rno));
                mma_bf16(acc[0][np*2],   ah0, bh[0], bh[2]);
                mma_bf16(acc[1][np*2],   ah1, bh[0], bh[2]);
                mma_bf16(acc[0][np*2+1], ah0, bh[1], bh[3]);
                mma_bf16(acc[1][np*2+1], ah1, bh[1], bh[3]);
                mma_bf16(acc[0][np*2],   ah0, bl[0], bl[2]);
                mma_bf16(acc[1][np*2],   ah1, bl[0], bl[2]);
                mma_bf16(acc[0][np*2+1], ah0, bl[1], bl[3]);
                mma_bf16(acc[1][np*2+1], ah1, bl[1], bl[3]);
                mma_bf16(acc[0][np*2],   al0, bh[0], bh[2]);
                mma_bf16(acc[1][np*2],   al1, bh[0], bh[2]);
                mma_bf16(acc[0][np*2+1], al0, bh[1], bh[3]);
                mma_bf16(acc[1][np*2+1], al1, bh[1], bh[3]);
            }
        }
        __syncthreads();
    }

    int qrow = lane >> 2, qcol = (lane & 3) * 2;
#pragma unroll
    for (int m = 0; m < 2; m++) {
        int row0 = m0 + wm*32 + m*16 + qrow;
#pragma unroll
        for (int nt = 0; nt < 8; nt++) {
            int col = n0 + wn*64 + nt*8 + qcol;
            float b0 = bias ? bias[col] : 0.f;
            float b1 = bias ? bias[col+1] : 0.f;
            float2 v0 = make_float2(acc[m][nt][0] + b0, acc[m][nt][1] + b1);
            float2 v1 = make_float2(acc[m][nt][2] + b0, acc[m][nt][3] + b1);
            *(float2*)(C + (size_t)row0 * N + col) = v0;
            *(float2*)(C + (size_t)(row0 + 8) * N + col) = v1;
        }
    }
}

// ---------------- weight prep ----------------
__global__ void wprep_t_kernel(const float* __restrict__ W, __nv_bfloat16* __restrict__ Th,
                               __nv_bfloat16* __restrict__ Tl, int K, int N) {
    __shared__ float tile[32][33];
    int k0 = blockIdx.x * 32, n0 = blockIdx.y * 32;
    int tx = threadIdx.x, ty = threadIdx.y;
    for (int j = 0; j < 32; j += 8)
        tile[ty + j][tx] = W[(size_t)(k0 + ty + j) * N + n0 + tx];
    __syncthreads();
    for (int j = 0; j < 32; j += 8) {
        float v = tile[tx][ty + j];
        size_t o = (size_t)(n0 + ty + j) * K + k0 + tx;
        __nv_bfloat16 h, l; bf16split(v, &h, &l);
        Th[o] = h; Tl[o] = l;
    }
}
__global__ void wprep_kernel(const float* __restrict__ W, __nv_bfloat16* __restrict__ H,
                             __nv_bfloat16* __restrict__ L, int n) {
    int i = blockIdx.x * 256 + threadIdx.x;
    if (i < n) { __nv_bfloat16 h, l; bf16split(W[i], &h, &l); H[i] = h; L[i] = l; }
}

// ---------------- layernorm -> bf16 split ----------------
__global__ void ln_kernel(const float* __restrict__ x, const float* __restrict__ g,
                          const float* __restrict__ bta) {
    int row = blockIdx.x;
    const float* xr = x + (size_t)row * DIM;
    int t = threadIdx.x;
    float v[4]; float s = 0.f;
#pragma unroll
    for (int i = 0; i < 4; i++) { v[i] = xr[t + 256*i]; s += v[i]; }
    __shared__ float red[256];
    red[t] = s; __syncthreads();
    for (int k = 128; k > 0; k >>= 1) { if (t < k) red[t] += red[t+k]; __syncthreads(); }
    float mu = red[0] * (1.0f/DIM); __syncthreads();
    float s2 = 0.f;
#pragma unroll
    for (int i = 0; i < 4; i++) { float d = v[i]-mu; s2 += d*d; }
    red[t] = s2; __syncthreads();
    for (int k = 128; k > 0; k >>= 1) { if (t < k) red[t] += red[t+k]; __syncthreads(); }
    float inv = 1.0f / sqrtf(red[0] * (1.0f/DIM) + 1e-5f);
#pragma unroll
    for (int i = 0; i < 4; i++) {
        int d = t + 256*i;
        float y = (v[i]-mu)*inv*g[d] + bta[d];
        __nv_bfloat16 h, l; bf16split(y, &h, &l);
        g_xnh[(size_t)row*DIM + d] = h;
        g_xnl[(size_t)row*DIM + d] = l;
    }
}

// ---------------- light attention: 3x64 chunks, online softmax, float4 LDS ----------------
__global__ __launch_bounds__(256) void light_attn_kernel() {
    extern __shared__ float lsm[];
    float* sq = lsm;
    float* sk = sq + 64*AP;
    float* sv = sk + 64*AP;
    float* sp = sv + 64*AP;
    int win = blockIdx.x, h = blockIdx.y, b = blockIdx.z;
    int t = threadIdx.x;
    for (int e = t; e < 64*64; e += 256) {
        int i = e >> 6, d = e & 63;
        int n = win*64 + i;
        sq[i*AP + d] = g_qkv[((size_t)(b*SEQ + n))*QKVD + h*64 + d] * 0.125f;
    }
    int qg = t >> 4, kg = t & 15;
    float m[4], l[4], acc[4][4];
#pragma unroll
    for (int u = 0; u < 4; u++) {
        m[u] = -FLT_MAX; l[u] = 0.f;
#pragma unroll
        for (int w = 0; w < 4; w++) acc[u][w] = 0.f;
    }

    for (int c = 0; c < 3; c++) {
        int nbase = (win - 1 + c) * 64;
        __syncthreads();
        for (int e = t; e < 64*64; e += 256) {
            int j = e >> 6, d = e & 63;
            int n = nbase + j;
            bool ok = (n >= 0 && n < SEQ);
            size_t base = ((size_t)(b*SEQ + n))*QKVD + h*64 + d;
            sk[j*AP + d] = ok ? g_qkv[base + 512]  : 0.f;
            sv[j*AP + d] = ok ? g_qkv[base + 1024] : 0.f;
        }
        __syncthreads();
        float s[4][4];
#pragma unroll
        for (int u = 0; u < 4; u++)
#pragma unroll
            for (int w = 0; w < 4; w++) s[u][w] = 0.f;
        for (int d4 = 0; d4 < 64; d4 += 4) {
            float4 q4[4], k4[4];
#pragma unroll
            for (int u = 0; u < 4; u++) q4[u] = *(const float4*)&sq[(qg + 16*u)*AP + d4];
#pragma unroll
            for (int w = 0; w < 4; w++) k4[w] = *(const float4*)&sk[(kg + 16*w)*AP + d4];
#pragma unroll
            for (int u = 0; u < 4; u++)
#pragma unroll
                for (int w = 0; w < 4; w++) {
                    s[u][w] = fmaf(q4[u].x, k4[w].x, s[u][w]);
                    s[u][w] = fmaf(q4[u].y, k4[w].y, s[u][w]);
                    s[u][w] = fmaf(q4[u].z, k4[w].z, s[u][w]);
                    s[u][w] = fmaf(q4[u].w, k4[w].w, s[u][w]);
                }
        }
#pragma unroll
        for (int u = 0; u < 4; u++) {
            int iabs = win*64 + qg + 16*u;
            float cm = -FLT_MAX;
#pragma unroll
            for (int w = 0; w < 4; w++) {
                int jabs = nbase + kg + 16*w;
                bool valid = (jabs >= 0) && (jabs < SEQ) && (abs(iabs - jabs) <= WIN);
                float sx = valid ? s[u][w] : -FLT_MAX;
                s[u][w] = sx;
                cm = fmaxf(cm, sx);
            }
#pragma unroll
            for (int off = 1; off < 16; off <<= 1)
                cm = fmaxf(cm, __shfl_xor_sync(0xFFFFFFFFu, cm, off));
            float mn = fmaxf(m[u], cm);
            float scale = __expf(m[u] - mn);
            bool anyvalid = (mn != -FLT_MAX);
            float ls = 0.f;
#pragma unroll
            for (int w = 0; w < 4; w++) {
                float p = anyvalid ? __expf(s[u][w] - mn) : 0.f;
                sp[(qg + 16*u)*AP + kg + 16*w] = p;
                ls += p;
            }
#pragma unroll
            for (int off = 1; off < 16; off <<= 1)
                ls += __shfl_xor_sync(0xFFFFFFFFu, ls, off);
            l[u] = l[u]*scale + ls;
            m[u] = mn;
#pragma unroll
            for (int w = 0; w < 4; w++) acc[u][w] *= scale;
        }
        __syncwarp();
        for (int k4i = 0; k4i < 64; k4i += 4) {
            float4 p4[4];
#pragma unroll
            for (int u = 0; u < 4; u++) p4[u] = *(const float4*)&sp[(qg + 16*u)*AP + k4i];
#pragma unroll
            for (int j = 0; j < 4; j++) {
                float4 v4 = *(const float4*)&sv[(k4i + j)*AP + 4*kg];
                float pj[4] = {(&p4[0].x)[j], (&p4[1].x)[j], (&p4[2].x)[j], (&p4[3].x)[j]};
#pragma unroll
                for (int u = 0; u < 4; u++) {
                    acc[u][0] = fmaf(pj[u], v4.x, acc[u][0]);
                    acc[u][1] = fmaf(pj[u], v4.y, acc[u][1]);
                    acc[u][2] = fmaf(pj[u], v4.z, acc[u][2]);
                    acc[u][3] = fmaf(pj[u], v4.w, acc[u][3]);
                }
            }
        }
        __syncwarp();
    }
#pragma unroll
    for (int u = 0; u < 4; u++) {
        float invl = 1.0f / l[u];
        int iabs = win*64 + qg + 16*u;
#pragma unroll
        for (int w = 0; w < 4; w++) {
            float y = acc[u][w] * invl;
            size_t o = ((size_t)(b*SEQ + iabs))*HDIM + h*64 + 4*kg + w;
            __nv_bfloat16 hh, ll; bf16split(y, &hh, &ll);
            g_lah[o] = hh; g_lal[o] = ll;
        }
    }
}

// ---------------- routing scores ----------------
__global__ void route_score_kernel(const float* __restrict__ x,
                                   const float* __restrict__ qt,
                                   const float* __restrict__ kt) {
    int row = blockIdx.x;
    int t = threadIdx.x;
    const float* xr = x + (size_t)row * DIM;
    float sq = 0.f, sk = 0.f;
#pragma unroll
    for (int i = t; i < DIM; i += 256) {
        float v = xr[i];
        sq = fmaf(v, qt[i], sq);
        sk = fmaf(v, kt[i], sk);
    }
    __shared__ float r1[256], r2[256];
    r1[t] = sq; r2[t] = sk; __syncthreads();
    for (int k = 128; k > 0; k >>= 1) {
        if (t < k) { r1[t] += r1[t+k]; r2[t] += r2[t+k]; }
        __syncthreads();
    }
    if (t == 0) { g_sq[row] = r1[0]; g_skv[row] = r2[0]; }
}

// ---------------- coordinate descent + exact top-k (bitonic) ----------------
__global__ __launch_bounds__(1024) void route_select_kernel() {
    extern __shared__ unsigned char rsm[];
    unsigned long long* key = (unsigned long long*)rsm;
    float* s  = (float*)(key + SEQ);
    float* bb = s + SEQ;
    __shared__ float red[1024];
    int b = blockIdx.x, which = blockIdx.y;
    int t = threadIdx.x;
    const float* src = which ? g_skv : g_sq;
    for (int i = t; i < SEQ; i += 1024) { float v = src[b*SEQ + i]; s[i] = v; bb[i] = -v; }
    __syncthreads();
    float cur = 4.0f;
    const float logk = logf(1152.0f);
    float a = 0.f;
    for (int it = 0; it < 20; it++) {
        float m = -FLT_MAX;
        for (int i = t; i < SEQ; i += 1024) m = fmaxf(m, (s[i] + bb[i]) / cur);
        red[t] = m; __syncthreads();
        for (int k = 512; k > 0; k >>= 1) { if (t < k) red[t] = fmaxf(red[t], red[t+k]); __syncthreads(); }
        m = red[0]; __syncthreads();
        float sum = 0.f;
        for (int i = t; i < SEQ; i += 1024) sum += expf((s[i] + bb[i]) / cur - m);
        red[t] = sum; __syncthreads();
        for (int k = 512; k > 0; k >>= 1) { if (t < k) red[t] += red[t+k]; __syncthreads(); }
        float lse = m + logf(red[0]);
        a = cur * (logk - lse);
        __syncthreads();
        for (int i = t; i < SEQ; i += 1024) bb[i] = -fmaxf(s[i] + a, 0.f);
        cur = fmaxf(cur * 0.7f, 0.03f);
        __syncthreads();
    }
    for (int i = t; i < SEQ; i += 1024) {
        float ta = s[i] + a;
        float sc = expf((ta + bb[i]) / cur);
        unsigned int sb = __float_as_uint(sc);
        key[i] = ((unsigned long long)sb << 32)
               | (unsigned long long)(0xFFFFFFFFu - (unsigned)i);
    }
    __syncthreads();
    for (int size = 2; size <= SEQ; size <<= 1) {
        for (int stride = size >> 1; stride > 0; stride >>= 1) {
            for (int i = t; i < SEQ; i += 1024) {
                int j = i ^ stride;
                if (j > i) {
                    bool desc = ((i & size) == 0);
                    unsigned long long ki = key[i], kj = key[j];
                    if ((ki < kj) == desc) { key[i] = kj; key[j] = ki; }
                }
            }
            __syncthreads();
        }
    }
    if (t < NSEL) {
        unsigned idxv = 0xFFFFFFFFu - (unsigned)(key[t] & 0xFFFFFFFFull);
        g_idx[(which*BATCH + b)*NSEL + t] = (int)idxv;
    }
}

// ---------------- gather routed + rmsnorm -> bf16 split ----------------
__global__ void gather_rms_kernel(const float* __restrict__ x,
                                  const float* __restrict__ gamma) {
    int j = blockIdx.x, b = blockIdx.y, which = blockIdx.z;
    int idx = g_idx[(which*BATCH + b)*NSEL + j];
    const float* xr = x + ((size_t)b*SEQ + idx)*DIM;
    int t = threadIdx.x;
    float v[4]; float ss = 0.f;
#pragma unroll
    for (int i = 0; i < 4; i++) { v[i] = xr[t + 256*i]; ss += v[i]*v[i]; }
    __shared__ float red[256];
    red[t] = ss; __syncthreads();
    for (int k = 128; k > 0; k >>= 1) { if (t < k) red[t] += red[t+k]; __syncthreads(); }
    float nrm = sqrtf(red[0]);
    float scale = 32.0f / fmaxf(nrm, 1e-12f);
    size_t base = (((size_t)which*BATCH + b)*NSEL + j)*DIM;
#pragma unroll
    for (int i = 0; i < 4; i++) {
        int d = t + 256*i;
        float y = v[i]*scale*gamma[d];
        __nv_bfloat16 h, l; bf16split(y, &h, &l);
        g_rth[base + d] = h; g_rtl[base + d] = l;
    }
}

// ---------------- rope on heavy q ----------------
__global__ void rope_q_kernel() {
    int e = blockIdx.x*256 + threadIdx.x;
    int d = e & 31;
    int h = (e >> 5) & 7;
    int j = (e >> 8) & 1023;
    int b = e >> 18;
    int tpos = g_idx[b*NSEL + j];
    float invf = powf(10000.0f, -(float)d / 32.0f);
    float th = (float)tpos * invf;
    float c, sn; sincosf(th, &sn, &c);
    size_t base = ((size_t)(b*NSEL + j))*HDIM + h*DHEAD;
    float x1 = g_qh[base + d], x2 = g_qh[base + d + 32];
    g_qh[base + d]      = x1*c - x2*sn;
    g_qh[base + d + 32] = x2*c + x1*sn;
}

// ---------------- pack k/v with rope + null kv ----------------
__global__ void pack_kv_kernel(const float* __restrict__ null_kv) {
    int e = blockIdx.x*256 + threadIdx.x;
    if (e >= BATCH*HEADS*KVLEN*32) return;
    int d  = e & 31;
    int jj = (e >> 5) % KVLEN;
    int hb = (e >> 5) / KVLEN;
    int h = hb & 7, b = hb >> 3;
    size_t obase = ((size_t)(b*HEADS + h)*KVLEN + jj)*DHEAD;
    if (jj == 0) {
        g_k[obase + d]      = null_kv[h*DHEAD + d];
        g_k[obase + d + 32] = null_kv[h*DHEAD + d + 32];
        g_v[obase + d]      = null_kv[HEADS*DHEAD + h*DHEAD + d];
        g_v[obase + d + 32] = null_kv[HEADS*DHEAD + h*DHEAD + d + 32];
    } else {
        int j = jj - 1;
        int tpos = g_idx[(BATCH + b)*NSEL + j];
        size_t ibase = ((size_t)(b*NSEL + j))*DIM + h*128;
        float k1 = g_kv[ibase + d], k2 = g_kv[ibase + d + 32];
        float invf = powf(10000.0f, -(float)d / 32.0f);
        float th = (float)tpos * invf;
        float c, sn; sincosf(th, &sn, &c);
        g_k[obase + d]      = k1*c - k2*sn;
        g_k[obase + d + 32] = k2*c + k1*sn;
        g_v[obase + d]      = g_kv[ibase + 64 + d];
        g_v[obase + d + 32] = g_kv[ibase + 64 + d + 32];
    }
}

// ---------------- heavy attention: 64-key chunks, float4 LDS ----------------
__global__ __launch_bounds__(256) void heavy_attn_kernel() {
    extern __shared__ float hsm[];
    float* sq = hsm;
    float* sk = sq + 64*AP;
    float* sv = sk + 64*AP;
    float* sp = sv + 64*AP;
    int qt = blockIdx.x, h = blockIdx.y, b = blockIdx.z;
    int t = threadIdx.x;
    for (int e = t; e < 64*64; e += 256) {
        int i = e >> 6, d = e & 63;
        sq[i*AP + d] = g_qh[((size_t)(b*NSEL + qt*64 + i))*HDIM + h*64 + d] * 0.125f;
    }
    int qg = t >> 4, kg = t & 15;
    float m[4], l[4], acc[4][4];
#pragma unroll
    for (int u = 0; u < 4; u++) {
        m[u] = -FLT_MAX; l[u] = 0.f;
#pragma unroll
        for (int w = 0; w < 4; w++) acc[u][w] = 0.f;
    }
    size_t kvbase = ((size_t)(b*HEADS + h))*KVLEN*DHEAD;
    for (int c0 = 0; c0 < KVLEN; c0 += 64) {
        int cnt = min(64, KVLEN - c0);
        __syncthreads();
        for (int e = t; e < 64*64; e += 256) {
            int j = e >> 6, d = e & 63;
            bool ok = j < cnt;
            sk[j*AP + d] = ok ? g_k[kvbase + (size_t)(c0 + j)*DHEAD + d] : 0.f;
            sv[j*AP + d] = ok ? g_v[kvbase + (size_t)(c0 + j)*DHEAD + d] : 0.f;
        }
        __syncthreads();
        float s[4][4];
#pragma unroll
        for (int u = 0; u < 4; u++)
#pragma unroll
            for (int w = 0; w < 4; w++) s[u][w] = 0.f;
        for (int d4 = 0; d4 < 64; d4 += 4) {
            float4 q4[4], k4[4];
#pragma unroll
            for (int u = 0; u < 4; u++) q4[u] = *(const float4*)&sq[(qg + 16*u)*AP + d4];
#pragma unroll
            for (int w = 0; w < 4; w++) k4[w] = *(const float4*)&sk[(kg + 16*w)*AP + d4];
#pragma unroll
            for (int u = 0; u < 4; u++)
#pragma unroll
                for (int w = 0; w < 4; w++) {
                    s[u][w] = fmaf(q4[u].x, k4[w].x, s[u][w]);
                    s[u][w] = fmaf(q4[u].y, k4[w].y, s[u][w]);
                    s[u][w] = fmaf(q4[u].z, k4[w].z, s[u][w]);
                    s[u][w] = fmaf(q4[u].w, k4[w].w, s[u][w]);
                }
        }
#pragma unroll
        for (int u = 0; u < 4; u++) {
            float cm = -FLT_MAX;
#pragma unroll
            for (int w = 0; w < 4; w++) {
                float sx = (kg + 16*w < cnt) ? s[u][w] : -FLT_MAX;
                s[u][w] = sx;
                cm = fmaxf(cm, sx);
            }
#pragma unroll
            for (int off = 1; off < 16; off <<= 1)
                cm = fmaxf(cm, __shfl_xor_sync(0xFFFFFFFFu, cm, off));
            float mn = fmaxf(m[u], cm);
            float scale = __expf(m[u] - mn);
            float ls = 0.f;
#pragma unroll
            for (int w = 0; w < 4; w++) {
                float p = (kg + 16*w < cnt) ? __expf(s[u][w] - mn) : 0.f;
                sp[(qg + 16*u)*AP + kg + 16*w] = p;
                ls += p;
            }
#pragma unroll
            for (int off = 1; off < 16; off <<= 1)
                ls += __shfl_xor_sync(0xFFFFFFFFu, ls, off);
            l[u] = l[u]*scale + ls;
            m[u] = mn;
#pragma unroll
            for (int w = 0; w < 4; w++) acc[u][w] *= scale;
        }
        __syncwarp();
        for (int k4i = 0; k4i < 64; k4i += 4) {
            float4 p4[4];
#pragma unroll
            for (int u = 0; u < 4; u++) p4[u] = *(const float4*)&sp[(qg + 16*u)*AP + k4i];
#pragma unroll
            for (int j = 0; j < 4; j++) {
                float4 v4 = *(const float4*)&sv[(k4i + j)*AP + 4*kg];
                float pj[4] = {(&p4[0].x)[j], (&p4[1].x)[j], (&p4[2].x)[j], (&p4[3].x)[j]};
#pragma unroll
                for (int u = 0; u < 4; u++) {
                    acc[u][0] = fmaf(pj[u], v4.x, acc[u][0]);
                    acc[u][1] = fmaf(pj[u], v4.y, acc[u][1]);
                    acc[u][2] = fmaf(pj[u], v4.z, acc[u][2]);
                    acc[u][3] = fmaf(pj[u], v4.w, acc[u][3]);
                }
            }
        }
        __syncwarp();
    }
#pragma unroll
    for (int u = 0; u < 4; u++) {
        float invl = 1.0f / l[u];
#pragma unroll
        for (int w = 0; w < 4; w++) {
            float y = acc[u][w] * invl;
            size_t o = ((size_t)(b*NSEL + qt*64 + qg + 16*u))*HDIM + h*64 + 4*kg + w;
            __nv_bfloat16 hh, ll; bf16split(y, &hh, &ll);
            g_hah[o] = hh; g_hal[o] = ll;
        }
    }
}

// ---------------- scatter ----------------
__global__ void scatter_kernel(float* __restrict__ out, const float* __restrict__ nullq) {
    int j = blockIdx.x & 1023, b = blockIdx.x >> 10;
    int i = g_idx[b*NSEL + j];
    float* orow = out + ((size_t)b*SEQ + i)*DIM;
    const float* hrow = g_ho + ((size_t)(b*NSEL + j))*DIM;
    for (int d = threadIdx.x; d < DIM; d += 256)
        orow[d] += hrow[d] - nullq[d];
}

// ---------------- launch ----------------
extern "C" void kernel_launch(void* const* d_in, const int* in_sizes, int n_in,
                              void* d_out, int out_size) {
    const float* x       = (const float*)d_in[0];
    const float* ln_g    = (const float*)d_in[1];
    const float* ln_b    = (const float*)d_in[2];
    const float* qkv_w   = (const float*)d_in[3];
    const float* lout_w  = (const float*)d_in[4];
    const float* q_tok   = (const float*)d_in[5];
    const float* kv_tok  = (const float*)d_in[6];
    const float* hgamma  = (const float*)d_in[7];
    const float* hq_w    = (const float*)d_in[8];
    const float* hkv_w   = (const float*)d_in[9];
    const float* hnullkv = (const float*)d_in[10];
    const float* hout_w  = (const float*)d_in[11];
    const float* nullq   = (const float*)d_in[12];
    float* out = (float*)d_out;

    static cudaStream_t s2 = nullptr;
    static cudaEvent_t evFork = nullptr, evJoin = nullptr;
    if (!s2) {
        cudaStreamCreateWithFlags(&s2, cudaStreamNonBlocking);
        cudaEventCreateWithFlags(&evFork, cudaEventDisableTiming);
        cudaEventCreateWithFlags(&evJoin, cudaEventDisableTiming);
    }

    float *p_qkv, *p_qh, *p_kv, *p_ho;
    __nv_bfloat16 *p_xnh, *p_xnl, *p_lah, *p_lal, *p_rth, *p_rtl, *p_hah, *p_hal;
    __nv_bfloat16 *p_wqh, *p_wql, *p_wlh, *p_wll, *p_whqh, *p_whql, *p_wkh, *p_wkl, *p_woh, *p_wol;
    cudaGetSymbolAddress((void**)&p_qkv, g_qkv);
    cudaGetSymbolAddress((void**)&p_qh, g_qh);
    cudaGetSymbolAddress((void**)&p_kv, g_kv);
    cudaGetSymbolAddress((void**)&p_ho, g_ho);
    cudaGetSymbolAddress((void**)&p_xnh, g_xnh); cudaGetSymbolAddress((void**)&p_xnl, g_xnl);
    cudaGetSymbolAddress((void**)&p_lah, g_lah); cudaGetSymbolAddress((void**)&p_lal, g_lal);
    cudaGetSymbolAddress((void**)&p_rth, g_rth); cudaGetSymbolAddress((void**)&p_rtl, g_rtl);
    cudaGetSymbolAddress((void**)&p_hah, g_hah); cudaGetSymbolAddress((void**)&p_hal, g_hal);
    cudaGetSymbolAddress((void**)&p_wqh, w_qkvh); cudaGetSymbolAddress((void**)&p_wql, w_qkvl);
    cudaGetSymbolAddress((void**)&p_wlh, w_louth); cudaGetSymbolAddress((void**)&p_wll, w_loutl);
    cudaGetSymbolAddress((void**)&p_whqh, w_hqh); cudaGetSymbolAddress((void**)&p_whql, w_hql);
    cudaGetSymbolAddress((void**)&p_wkh, w_hkvh); cudaGetSymbolAddress((void**)&p_wkl, w_hkvl);
    cudaGetSymbolAddress((void**)&p_woh, w_houth); cudaGetSymbolAddress((void**)&p_wol, w_houtl);

    const int LSMEM = 4*64*AP*4;                 // 69632
    const int HSMEM = 4*64*AP*4;
    const int RSMEM = SEQ*8 + 2*SEQ*4;
    const int GSMEM = 65536 + 1024;
    cudaFuncSetAttribute(light_attn_kernel,  cudaFuncAttributeMaxDynamicSharedMemorySize, LSMEM);
    cudaFuncSetAttribute(heavy_attn_kernel,  cudaFuncAttributeMaxDynamicSharedMemorySize, HSMEM);
    cudaFuncSetAttribute(route_select_kernel, cudaFuncAttributeMaxDynamicSharedMemorySize, RSMEM);
    cudaFuncSetAttribute(bmm_kernel, cudaFuncAttributeMaxDynamicSharedMemorySize, GSMEM);

    cudaEventRecord(evFork, 0);
    cudaStreamWaitEvent(s2, evFork, 0);

    // ======== stream 0: light path ========
    wprep_t_kernel<<<dim3(DIM/32, QKVD/32), dim3(32,8)>>>(qkv_w, p_wqh, p_wql, DIM, QKVD);
    ln_kernel<<<BATCH*SEQ, 256>>>(x, ln_g, ln_b);
    bmm_kernel<<<dim3(QKVD/128, (BATCH*SEQ)/128), 256, GSMEM>>>(
        p_xnh, p_xnl, p_wqh, p_wql, p_qkv, BATCH*SEQ, QKVD, DIM, nullptr);
    light_attn_kernel<<<dim3(NWIN, HEADS, BATCH), 256, LSMEM>>>();
    wprep_t_kernel<<<dim3(HDIM/32, DIM/32), dim3(32,8)>>>(lout_w, p_wlh, p_wll, HDIM, DIM);
    bmm_kernel<<<dim3(DIM/128, (BATCH*SEQ)/128), 256, GSMEM>>>(
        p_lah, p_lal, p_wlh, p_wll, out, BATCH*SEQ, DIM, HDIM, nullq);

    // ======== stream s2: routing + heavy path ========
    wprep_kernel<<<(DIM*DIM + 255)/256, 256, 0, s2>>>(hkv_w, p_wkh, p_wkl, DIM*DIM);
    wprep_t_kernel<<<dim3(DIM/32, HDIM/32), dim3(32,8), 0, s2>>>(hq_w, p_whqh, p_whql, DIM, HDIM);
    wprep_t_kernel<<<dim3(HDIM/32, DIM/32), dim3(32,8), 0, s2>>>(hout_w, p_woh, p_wol, HDIM, DIM);
    route_score_kernel<<<BATCH*SEQ, 256, 0, s2>>>(x, q_tok, kv_tok);
    route_select_kernel<<<dim3(BATCH, 2), 1024, RSMEM, s2>>>();
    gather_rms_kernel<<<dim3(NSEL, BATCH, 2), 256, 0, s2>>>(x, hgamma);
    bmm_kernel<<<dim3(HDIM/128, (BATCH*NSEL)/128), 256, GSMEM, s2>>>(
        p_rth, p_rtl, p_whqh, p_whql, p_qh, BATCH*NSEL, HDIM, DIM, nullptr);
    rope_q_kernel<<<(BATCH*NSEL*HEADS*32)/256, 256, 0, s2>>>();
    bmm_kernel<<<dim3(DIM/128, (BATCH*NSEL)/128), 256, GSMEM, s2>>>(
        p_rth + (size_t)BATCH*NSEL*DIM, p_rtl + (size_t)BATCH*NSEL*DIM,
        p_wkh, p_wkl, p_kv, BATCH*NSEL, DIM, DIM, nullptr);
    pack_kv_kernel<<<(BATCH*HEADS*KVLEN*32 + 255)/256, 256, 0, s2>>>(hnullkv);
    heavy_attn_kernel<<<dim3(16, HEADS, BATCH), 256, HSMEM, s2>>>();
    bmm_kernel<<<dim3(DIM/128, (BATCH*NSEL)/128), 256, GSMEM, s2>>>(
        p_hah, p_hal, p_woh, p_wol, p_ho, BATCH*NSEL, DIM, HDIM, nullptr);

    cudaEventRecord(evJoin, s2);
    cudaStreamWaitEvent(0, evJoin, 0);
    scatter_kernel<<<BATCH*NSEL, 256>>>(out, nullq);
}

// round 17
// speedup vs baseline: 1.3480x; 1.1055x over previous
// R17: GEMM split-3 bf16 -> split-2 fp16 (2 mma, 3 smem arrays): -33% tensor work, -25% loads.
#include <cuda_runtime.h>
#include <cuda_fp16.h>
#include <math.h>
#include <float.h>
#include <stdint.h>

#define BATCH 2
#define SEQ   8192
#define DIM   1024
#define HEADS 8
#define DHEAD 64
#define HDIM  512
#define QKVD  1536
#define WIN   64
#define NWIN  128
#define NSEL  1024
#define KVLEN 1025
#define AP    68

// ---------------- scratch ----------------
__device__ float g_qkv[(size_t)BATCH*SEQ*QKVD];
__device__ float g_sq[BATCH*SEQ];
__device__ float g_skv[BATCH*SEQ];
__device__ int   g_idx[2*BATCH*NSEL];
__device__ float g_qh[(size_t)BATCH*NSEL*HDIM];
__device__ float g_kv[(size_t)BATCH*NSEL*DIM];
__device__ float g_k[(size_t)BATCH*HEADS*KVLEN*DHEAD];
__device__ float g_v[(size_t)BATCH*HEADS*KVLEN*DHEAD];
__device__ float g_ho[(size_t)BATCH*NSEL*DIM];
// fp16 split-2 activations
__device__ __half g_xnh[(size_t)BATCH*SEQ*DIM],  g_xnl[(size_t)BATCH*SEQ*DIM];
__device__ __half g_lah[(size_t)BATCH*SEQ*HDIM], g_lal[(size_t)BATCH*SEQ*HDIM];
__device__ __half g_rth[(size_t)2*BATCH*NSEL*DIM], g_rtl[(size_t)2*BATCH*NSEL*DIM];
__device__ __half g_hah[(size_t)BATCH*NSEL*HDIM], g_hal[(size_t)BATCH*NSEL*HDIM];
// fp16 weights, stored [N][K] (B^T), single rounded copy
__device__ __half w_qkvh[(size_t)QKVD*DIM];
__device__ __half w_louth[(size_t)DIM*HDIM];
__device__ __half w_hqh[(size_t)HDIM*DIM];
__device__ __half w_hkvh[(size_t)DIM*DIM];
__device__ __half w_houth[(size_t)DIM*HDIM];

// ---------------- helpers ----------------
__device__ __forceinline__ uint32_t smem_u32(const void* p) {
    uint32_t a;
    asm("{ .reg .u64 t; cvta.to.shared.u64 t, %1; cvt.u32.u64 %0, t; }" : "=r"(a) : "l"(p));
    return a;
}
#define SWZ64(o)  ((o) ^ (((o) >> 3) & 0x30))

__device__ __forceinline__ void ldm4(uint32_t* r, uint32_t addr) {
    asm volatile("ldmatrix.sync.aligned.m8n8.x4.shared.b16 {%0,%1,%2,%3}, [%4];"
        : "=r"(r[0]), "=r"(r[1]), "=r"(r[2]), "=r"(r[3]) : "r"(addr));
}
__device__ __forceinline__ void mma_f16(float* d, const uint32_t* a, uint32_t b0, uint32_t b1) {
    asm volatile("mma.sync.aligned.m16n8k16.row.col.f32.f16.f16.f32 "
        "{%0,%1,%2,%3}, {%4,%5,%6,%7}, {%8,%9}, {%0,%1,%2,%3};"
        : "+f"(d[0]), "+f"(d[1]), "+f"(d[2]), "+f"(d[3])
        : "r"(a[0]), "r"(a[1]), "r"(a[2]), "r"(a[3]), "r"(b0), "r"(b1));
}
__device__ __forceinline__ void cpasync16(uint32_t dst, const void* src) {
    asm volatile("cp.async.cg.shared.global [%0], [%1], 16;" :: "r"(dst), "l"(src));
}
__device__ __forceinline__ void f16split(float v, __half* hi, __half* lo) {
    __half h = __float2half_rn(v);
    *hi = h;
    *lo = __float2half_rn(v - __half2float(h));
}

// ---------------- pipelined mma.sync split-2 fp16 GEMM: 128x128 tile ----------------
// C = Ah@Bh^T + Al@Bh^T. grid (N/128, M/128), 256 threads, 2-stage cp.async, stage 24KB.
__global__ __launch_bounds__(256, 2) void bmm_kernel(
        const __half* __restrict__ Ah, const __half* __restrict__ Al,
        const __half* __restrict__ Bh,
        float* __restrict__ C, int M, int N, int K, const float* __restrict__ bias) {
    extern __shared__ unsigned char dsm_raw[];
    unsigned char* sb = (unsigned char*)(((uintptr_t)dsm_raw + 1023) & ~(uintptr_t)1023);
    int t = threadIdx.x, wid = t >> 5, lane = t & 31;
    int n0 = blockIdx.x * 128, m0 = blockIdx.y * 128;
    uint32_t uS = smem_u32(sb);
    int wm = wid & 3, wn = wid >> 2;

    float acc[2][8][4];
#pragma unroll
    for (int m = 0; m < 2; m++)
#pragma unroll
        for (int n = 0; n < 8; n++)
#pragma unroll
            for (int q = 0; q < 4; q++) acc[m][n][q] = 0.f;

    int fr = lane & 15;
    uint32_t fb = (uint32_t)(lane >> 4) * 16;
    int nk = K >> 5;

    auto load_stage = [&](int s) {
        int k0 = s << 5;
        uint32_t stb = uS + (uint32_t)(s & 1) * 24576;
#pragma unroll
        for (int i = 0; i < 2; i++) {
            int chunk = t + i * 256;
            int r = chunk >> 2, c = chunk & 3;
            uint32_t so = SWZ64((uint32_t)(r * 64 + c * 16));
            size_t goA = (size_t)(m0 + r) * K + k0 + c * 8;
            size_t goB = (size_t)(n0 + r) * K + k0 + c * 8;
            cpasync16(stb + so,          Ah + goA);
            cpasync16(stb + 8192  + so,  Al + goA);
            cpasync16(stb + 16384 + so,  Bh + goB);
        }
        asm volatile("cp.async.commit_group;" ::: "memory");
    };

    load_stage(0);
    for (int s = 0; s < nk; s++) {
        if (s + 1 < nk) {
            load_stage(s + 1);
            asm volatile("cp.async.wait_group 1;" ::: "memory");
        } else {
            asm volatile("cp.async.wait_group 0;" ::: "memory");
        }
        __syncthreads();
        uint32_t stb = uS + (uint32_t)(s & 1) * 24576;
        uint32_t uAh = stb, uAl = stb + 8192, uBh = stb + 16384;
#pragma unroll
        for (int kk = 0; kk < 2; kk++) {
            uint32_t kb = (uint32_t)kk * 32 + fb;
            uint32_t ah0[4], ah1[4], al0[4], al1[4];
            {
                uint32_t r0o = (uint32_t)(wm*32 + fr) * 64 + kb;
                uint32_t r1o = (uint32_t)(wm*32 + 16 + fr) * 64 + kb;
                ldm4(ah0, uAh + SWZ64(r0o));
                ldm4(ah1, uAh + SWZ64(r1o));
                ldm4(al0, uAl + SWZ64(r0o));
                ldm4(al1, uAl + SWZ64(r1o));
            }
#pragma unroll
            for (int np = 0; np < 4; np++) {
                uint32_t bh[4];
                uint32_t rno = (uint32_t)(wn*64 + np*16 + fr) * 64 + kb;
                ldm4(bh, uBh + SWZ64(rno));
                mma_f16(acc[0][np*2],   ah0, bh[0], bh[2]);
                mma_f16(acc[1][np*2],   ah1, bh[0], bh[2]);
                mma_f16(acc[0][np*2+1], ah0, bh[1], bh[3]);
                mma_f16(acc[1][np*2+1], ah1, bh[1], bh[3]);
                mma_f16(acc[0][np*2],   al0, bh[0], bh[2]);
                mma_f16(acc[1][np*2],   al1, bh[0], bh[2]);
                mma_f16(acc[0][np*2+1], al0, bh[1], bh[3]);
                mma_f16(acc[1][np*2+1], al1, bh[1], bh[3]);
            }
        }
        __syncthreads();
    }

    int qrow = lane >> 2, qcol = (lane & 3) * 2;
#pragma unroll
    for (int m = 0; m < 2; m++) {
        int row0 = m0 + wm*32 + m*16 + qrow;
#pragma unroll
        for (int nt = 0; nt < 8; nt++) {
            int col = n0 + wn*64 + nt*8 + qcol;
            float b0 = bias ? bias[col] : 0.f;
            float b1 = bias ? bias[col+1] : 0.f;
            float2 v0 = make_float2(acc[m][nt][0] + b0, acc[m][nt][1] + b1);
            float2 v1 = make_float2(acc[m][nt][2] + b0, acc[m][nt][3] + b1);
            *(float2*)(C + (size_t)row0 * N + col) = v0;
            *(float2*)(C + (size_t)(row0 + 8) * N + col) = v1;
        }
    }
}

// ---------------- weight prep: W[K,N] fp32 -> Wt[N,K] fp16 ----------------
__global__ void wprep_t_kernel(const float* __restrict__ W, __half* __restrict__ Th,
                               int K, int N) {
    __shared__ float tile[32][33];
    int k0 = blockIdx.x * 32, n0 = blockIdx.y * 32;
    int tx = threadIdx.x, ty = threadIdx.y;
    for (int j = 0; j < 32; j += 8)
        tile[ty + j][tx] = W[(size_t)(k0 + ty + j) * N + n0 + tx];
    __syncthreads();
    for (int j = 0; j < 32; j += 8) {
        float v = tile[tx][ty + j];
        Th[(size_t)(n0 + ty + j) * K + k0 + tx] = __float2half_rn(v);
    }
}
__global__ void wprep_kernel(const float* __restrict__ W, __half* __restrict__ H, int n) {
    int i = blockIdx.x * 256 + threadIdx.x;
    if (i < n) H[i] = __float2half_rn(W[i]);
}

// ---------------- layernorm -> fp16 split-2 ----------------
__global__ void ln_kernel(const float* __restrict__ x, const float* __restrict__ g,
                          const float* __restrict__ bta) {
    int row = blockIdx.x;
    const float* xr = x + (size_t)row * DIM;
    int t = threadIdx.x;
    float v[4]; float s = 0.f;
#pragma unroll
    for (int i = 0; i < 4; i++) { v[i] = xr[t + 256*i]; s += v[i]; }
    __shared__ float red[256];
    red[t] = s; __syncthreads();
    for (int k = 128; k > 0; k >>= 1) { if (t < k) red[t] += red[t+k]; __syncthreads(); }
    float mu = red[0] * (1.0f/DIM); __syncthreads();
    float s2 = 0.f;
#pragma unroll
    for (int i = 0; i < 4; i++) { float d = v[i]-mu; s2 += d*d; }
    red[t] = s2; __syncthreads();
    for (int k = 128; k > 0; k >>= 1) { if (t < k) red[t] += red[t+k]; __syncthreads(); }
    float inv = 1.0f / sqrtf(red[0] * (1.0f/DIM) + 1e-5f);
#pragma unroll
    for (int i = 0; i < 4; i++) {
        int d = t + 256*i;
        float y = (v[i]-mu)*inv*g[d] + bta[d];
        __half h, l; f16split(y, &h, &l);
        g_xnh[(size_t)row*DIM + d] = h;
        g_xnl[(size_t)row*DIM + d] = l;
    }
}

// ---------------- light attention: 3x64 chunks, online softmax, float4 LDS ----------------
__global__ __launch_bounds__(256) void light_attn_kernel() {
    extern __shared__ float lsm[];
    float* sq = lsm;
    float* sk = sq + 64*AP;
    float* sv = sk + 64*AP;
    float* sp = sv + 64*AP;
    int win = blockIdx.x, h = blockIdx.y, b = blockIdx.z;
    int t = threadIdx.x;
    for (int e = t; e < 64*64; e += 256) {
        int i = e >> 6, d = e & 63;
        int n = win*64 + i;
        sq[i*AP + d] = g_qkv[((size_t)(b*SEQ + n))*QKVD + h*64 + d] * 0.125f;
    }
    int qg = t >> 4, kg = t & 15;
    float m[4], l[4], acc[4][4];
#pragma unroll
    for (int u = 0; u < 4; u++) {
        m[u] = -FLT_MAX; l[u] = 0.f;
#pragma unroll
        for (int w = 0; w < 4; w++) acc[u][w] = 0.f;
    }

    for (int c = 0; c < 3; c++) {
        int nbase = (win - 1 + c) * 64;
        __syncthreads();
        for (int e = t; e < 64*64; e += 256) {
            int j = e >> 6, d = e & 63;
            int n = nbase + j;
            bool ok = (n >= 0 && n < SEQ);
            size_t base = ((size_t)(b*SEQ + n))*QKVD + h*64 + d;
            sk[j*AP + d] = ok ? g_qkv[base + 512]  : 0.f;
            sv[j*AP + d] = ok ? g_qkv[base + 1024] : 0.f;
        }
        __syncthreads();
        float s[4][4];
#pragma unroll
        for (int u = 0; u < 4; u++)
#pragma unroll
            for (int w = 0; w < 4; w++) s[u][w] = 0.f;
        for (int d4 = 0; d4 < 64; d4 += 4) {
            float4 q4[4], k4[4];
#pragma unroll
            for (int u = 0; u < 4; u++) q4[u] = *(const float4*)&sq[(qg + 16*u)*AP + d4];
#pragma unroll
            for (int w = 0; w < 4; w++) k4[w] = *(const float4*)&sk[(kg + 16*w)*AP + d4];
#pragma unroll
            for (int u = 0; u < 4; u++)
#pragma unroll
                for (int w = 0; w < 4; w++) {
                    s[u][w] = fmaf(q4[u].x, k4[w].x, s[u][w]);
                    s[u][w] = fmaf(q4[u].y, k4[w].y, s[u][w]);
                    s[u][w] = fmaf(q4[u].z, k4[w].z, s[u][w]);
                    s[u][w] = fmaf(q4[u].w, k4[w].w, s[u][w]);
                }
        }
#pragma unroll
        for (int u = 0; u < 4; u++) {
            int iabs = win*64 + qg + 16*u;
            float cm = -FLT_MAX;
#pragma unroll
            for (int w = 0; w < 4; w++) {
                int jabs = nbase + kg + 16*w;
                bool valid = (jabs >= 0) && (jabs < SEQ) && (abs(iabs - jabs) <= WIN);
                float sx = valid ? s[u][w] : -FLT_MAX;
                s[u][w] = sx;
                cm = fmaxf(cm, sx);
            }
#pragma unroll
            for (int off = 1; off < 16; off <<= 1)
                cm = fmaxf(cm, __shfl_xor_sync(0xFFFFFFFFu, cm, off));
            float mn = fmaxf(m[u], cm);
            float scale = __expf(m[u] - mn);
            bool anyvalid = (mn != -FLT_MAX);
            float ls = 0.f;
#pragma unroll
            for (int w = 0; w < 4; w++) {
                float p = anyvalid ? __expf(s[u][w] - mn) : 0.f;
                sp[(qg + 16*u)*AP + kg + 16*w] = p;
                ls += p;
            }
#pragma unroll
            for (int off = 1; off < 16; off <<= 1)
                ls += __shfl_xor_sync(0xFFFFFFFFu, ls, off);
            l[u] = l[u]*scale + ls;
            m[u] = mn;
#pragma unroll
            for (int w = 0; w < 4; w++) acc[u][w] *= scale;
        }
        __syncwarp();
        for (int k4i = 0; k4i < 64; k4i += 4) {
            float4 p4[4];
#pragma unroll
            for (int u = 0; u < 4; u++) p4[u] = *(const float4*)&sp[(qg + 16*u)*AP + k4i];
#pragma unroll
            for (int j = 0; j < 4; j++) {
                float4 v4 = *(const float4*)&sv[(k4i + j)*AP + 4*kg];
                float pj[4] = {(&p4[0].x)[j], (&p4[1].x)[j], (&p4[2].x)[j], (&p4[3].x)[j]};
#pragma unroll
                for (int u = 0; u < 4; u++) {
                    acc[u][0] = fmaf(pj[u], v4.x, acc[u][0]);
                    acc[u][1] = fmaf(pj[u], v4.y, acc[u][1]);
                    acc[u][2] = fmaf(pj[u], v4.z, acc[u][2]);
                    acc[u][3] = fmaf(pj[u], v4.w, acc[u][3]);
                }
            }
        }
        __syncwarp();
    }
#pragma unroll
    for (int u = 0; u < 4; u++) {
        float invl = 1.0f / l[u];
        int iabs = win*64 + qg + 16*u;
#pragma unroll
        for (int w = 0; w < 4; w++) {
            float y = acc[u][w] * invl;
            size_t o = ((size_t)(b*SEQ + iabs))*HDIM + h*64 + 4*kg + w;
            __half hh, ll; f16split(y, &hh, &ll);
            g_lah[o] = hh; g_lal[o] = ll;
        }
    }
}

// ---------------- routing scores ----------------
__global__ void route_score_kernel(const float* __restrict__ x,
                                   const float* __restrict__ qt,
                                   const float* __restrict__ kt) {
    int row = blockIdx.x;
    int t = threadIdx.x;
    const float* xr = x + (size_t)row * DIM;
    float sq = 0.f, sk = 0.f;
#pragma unroll
    for (int i = t; i < DIM; i += 256) {
        float v = xr[i];
        sq = fmaf(v, qt[i], sq);
        sk = fmaf(v, kt[i], sk);
    }
    __shared__ float r1[256], r2[256];
    r1[t] = sq; r2[t] = sk; __syncthreads();
    for (int k = 128; k > 0; k >>= 1) {
        if (t < k) { r1[t] += r1[t+k]; r2[t] += r2[t+k]; }
        __syncthreads();
    }
    if (t == 0) { g_sq[row] = r1[0]; g_skv[row] = r2[0]; }
}

// ---------------- coordinate descent + exact top-k (bitonic) ----------------
__global__ __launch_bounds__(1024) void route_select_kernel() {
    extern __shared__ unsigned char rsm[];
    unsigned long long* key = (unsigned long long*)rsm;
    float* s  = (float*)(key + SEQ);
    float* bb = s + SEQ;
    __shared__ float red[1024];
    int b = blockIdx.x, which = blockIdx.y;
    int t = threadIdx.x;
    const float* src = which ? g_skv : g_sq;
    for (int i = t; i < SEQ; i += 1024) { float v = src[b*SEQ + i]; s[i] = v; bb[i] = -v; }
    __syncthreads();
    float cur = 4.0f;
    const float logk = logf(1152.0f);
    float a = 0.f;
    for (int it = 0; it < 20; it++) {
        float m = -FLT_MAX;
        for (int i = t; i < SEQ; i += 1024) m = fmaxf(m, (s[i] + bb[i]) / cur);
        red[t] = m; __syncthreads();
        for (int k = 512; k > 0; k >>= 1) { if (t < k) red[t] = fmaxf(red[t], red[t+k]); __syncthreads(); }
        m = red[0]; __syncthreads();
        float sum = 0.f;
        for (int i = t; i < SEQ; i += 1024) sum += expf((s[i] + bb[i]) / cur - m);
        red[t] = sum; __syncthreads();
        for (int k = 512; k > 0; k >>= 1) { if (t < k) red[t] += red[t+k]; __syncthreads(); }
        float lse = m + logf(red[0]);
        a = cur * (logk - lse);
        __syncthreads();
        for (int i = t; i < SEQ; i += 1024) bb[i] = -fmaxf(s[i] + a, 0.f);
        cur = fmaxf(cur * 0.7f, 0.03f);
        __syncthreads();
    }
    for (int i = t; i < SEQ; i += 1024) {
        float ta = s[i] + a;
        float sc = expf((ta + bb[i]) / cur);
        unsigned int sb = __float_as_uint(sc);
        key[i] = ((unsigned long long)sb << 32)
               | (unsigned long long)(0xFFFFFFFFu - (unsigned)i);
    }
    __syncthreads();
    for (int size = 2; size <= SEQ; size <<= 1) {
        for (int stride = size >> 1; stride > 0; stride >>= 1) {
            for (int i = t; i < SEQ; i += 1024) {
                int j = i ^ stride;
                if (j > i) {
                    bool desc = ((i & size) == 0);
                    unsigned long long ki = key[i], kj = key[j];
                    if ((ki < kj) == desc) { key[i] = kj; key[j] = ki; }
                }
            }
            __syncthreads();
        }
    }
    if (t < NSEL) {
        unsigned idxv = 0xFFFFFFFFu - (unsigned)(key[t] & 0xFFFFFFFFull);
        g_idx[(which*BATCH + b)*NSEL + t] = (int)idxv;
    }
}

// ---------------- gather routed + rmsnorm -> fp16 split-2 ----------------
__global__ void gather_rms_kernel(const float* __restrict__ x,
                                  const float* __restrict__ gamma) {
    int j = blockIdx.x, b = blockIdx.y, which = blockIdx.z;
    int idx = g_idx[(which*BATCH + b)*NSEL + j];
    const float* xr = x + ((size_t)b*SEQ + idx)*DIM;
    int t = threadIdx.x;
    float v[4]; float ss = 0.f;
#pragma unroll
    for (int i = 0; i < 4; i++) { v[i] = xr[t + 256*i]; ss += v[i]*v[i]; }
    __shared__ float red[256];
    red[t] = ss; __syncthreads();
    for (int k = 128; k > 0; k >>= 1) { if (t < k) red[t] += red[t+k]; __syncthreads(); }
    float nrm = sqrtf(red[0]);
    float scale = 32.0f / fmaxf(nrm, 1e-12f);
    size_t base = (((size_t)which*BATCH + b)*NSEL + j)*DIM;
#pragma unroll
    for (int i = 0; i < 4; i++) {
        int d = t + 256*i;
        float y = v[i]*scale*gamma[d];
        __half h, l; f16split(y, &h, &l);
        g_rth[base + d] = h; g_rtl[base + d] = l;
    }
}

// ---------------- rope on heavy q ----------------
__global__ void rope_q_kernel() {
    int e = blockIdx.x*256 + threadIdx.x;
    int d = e & 31;
    int h = (e >> 5) & 7;
    int j = (e >> 8) & 1023;
    int b = e >> 18;
    int tpos = g_idx[b*NSEL + j];
    float invf = powf(10000.0f, -(float)d / 32.0f);
    float th = (float)tpos * invf;
    float c, sn; sincosf(th, &sn, &c);
    size_t base = ((size_t)(b*NSEL + j))*HDIM + h*DHEAD;
    float x1 = g_qh[base + d], x2 = g_qh[base + d + 32];
    g_qh[base + d]      = x1*c - x2*sn;
    g_qh[base + d + 32] = x2*c + x1*sn;
}

// ---------------- pack k/v with rope + null kv ----------------
__global__ void pack_kv_kernel(const float* __restrict__ null_kv) {
    int e = blockIdx.x*256 + threadIdx.x;
    if (e >= BATCH*HEADS*KVLEN*32) return;
    int d  = e & 31;
    int jj = (e >> 5) % KVLEN;
    int hb = (e >> 5) / KVLEN;
    int h = hb & 7, b = hb >> 3;
    size_t obase = ((size_t)(b*HEADS + h)*KVLEN + jj)*DHEAD;
    if (jj == 0) {
        g_k[obase + d]      = null_kv[h*DHEAD + d];
        g_k[obase + d + 32] = null_kv[h*DHEAD + d + 32];
        g_v[obase + d]      = null_kv[HEADS*DHEAD + h*DHEAD + d];
        g_v[obase + d + 32] = null_kv[HEADS*DHEAD + h*DHEAD + d + 32];
    } else {
        int j = jj - 1;
        int tpos = g_idx[(BATCH + b)*NSEL + j];
        size_t ibase = ((size_t)(b*NSEL + j))*DIM + h*128;
        float k1 = g_kv[ibase + d], k2 = g_kv[ibase + d + 32];
        float invf = powf(10000.0f, -(float)d / 32.0f);
        float th = (float)tpos * invf;
        float c, sn; sincosf(th, &sn, &c);
        g_k[obase + d]      = k1*c - k2*sn;
        g_k[obase + d + 32] = k2*c + k1*sn;
        g_v[obase + d]      = g_kv[ibase + 64 + d];
        g_v[obase + d + 32] = g_kv[ibase + 64 + d + 32];
    }
}

// ---------------- heavy attention: 64-key chunks, float4 LDS ----------------
__global__ __launch_bounds__(256) void heavy_attn_kernel() {
    extern __shared__ float hsm[];
    float* sq = hsm;
    float* sk = sq + 64*AP;
    float* sv = sk + 64*AP;
    float* sp = sv + 64*AP;
    int qt = blockIdx.x, h = blockIdx.y, b = blockIdx.z;
    int t = threadIdx.x;
    for (int e = t; e < 64*64; e += 256) {
        int i = e >> 6, d = e & 63;
        sq[i*AP + d] = g_qh[((size_t)(b*NSEL + qt*64 + i))*HDIM + h*64 + d] * 0.125f;
    }
    int qg = t >> 4, kg = t & 15;
    float m[4], l[4], acc[4][4];
#pragma unroll
    for (int u = 0; u < 4; u++) {
        m[u] = -FLT_MAX; l[u] = 0.f;
#pragma unroll
        for (int w = 0; w < 4; w++) acc[u][w] = 0.f;
    }
    size_t kvbase = ((size_t)(b*HEADS + h))*KVLEN*DHEAD;
    for (int c0 = 0; c0 < KVLEN; c0 += 64) {
        int cnt = min(64, KVLEN - c0);
        __syncthreads();
        for (int e = t; e < 64*64; e += 256) {
            int j = e >> 6, d = e & 63;
            bool ok = j < cnt;
            sk[j*AP + d] = ok ? g_k[kvbase + (size_t)(c0 + j)*DHEAD + d] : 0.f;
            sv[j*AP + d] = ok ? g_v[kvbase + (size_t)(c0 + j)*DHEAD + d] : 0.f;
        }
        __syncthreads();
        float s[4][4];
#pragma unroll
        for (int u = 0; u < 4; u++)
#pragma unroll
            for (int w = 0; w < 4; w++) s[u][w] = 0.f;
        for (int d4 = 0; d4 < 64; d4 += 4) {
            float4 q4[4], k4[4];
#pragma unroll
            for (int u = 0; u < 4; u++) q4[u] = *(const float4*)&sq[(qg + 16*u)*AP + d4];
#pragma unroll
            for (int w = 0; w < 4; w++) k4[w] = *(const float4*)&sk[(kg + 16*w)*AP + d4];
#pragma unroll
            for (int u = 0; u < 4; u++)
#pragma unroll
                for (int w = 0; w < 4; w++) {
                    s[u][w] = fmaf(q4[u].x, k4[w].x, s[u][w]);
                    s[u][w] = fmaf(q4[u].y, k4[w].y, s[u][w]);
                    s[u][w] = fmaf(q4[u].z, k4[w].z, s[u][w]);
                    s[u][w] = fmaf(q4[u].w, k4[w].w, s[u][w]);
                }
        }
#pragma unroll
        for (int u = 0; u < 4; u++) {
            float cm = -FLT_MAX;
#pragma unroll
            for (int w = 0; w < 4; w++) {
                float sx = (kg + 16*w < cnt) ? s[u][w] : -FLT_MAX;
                s[u][w] = sx;
                cm = fmaxf(cm, sx);
            }
#pragma unroll
            for (int off = 1; off < 16; off <<= 1)
                cm = fmaxf(cm, __shfl_xor_sync(0xFFFFFFFFu, cm, off));
            float mn = fmaxf(m[u], cm);
            float scale = __expf(m[u] - mn);
            float ls = 0.f;
#pragma unroll
            for (int w = 0; w < 4; w++) {
                float p = (kg + 16*w < cnt) ? __expf(s[u][w] - mn) : 0.f;
                sp[(qg + 16*u)*AP + kg + 16*w] = p;
                ls += p;
            }
#pragma unroll
            for (int off = 1; off < 16; off <<= 1)
                ls += __shfl_xor_sync(0xFFFFFFFFu, ls, off);
            l[u] = l[u]*scale + ls;
            m[u] = mn;
#pragma unroll
            for (int w = 0; w < 4; w++) acc[u][w] *= scale;
        }
        __syncwarp();
        for (int k4i = 0; k4i < 64; k4i += 4) {
            float4 p4[4];
#pragma unroll
            for (int u = 0; u < 4; u++) p4[u] = *(const float4*)&sp[(qg + 16*u)*AP + k4i];
#pragma unroll
            for (int j = 0; j < 4; j++) {
                float4 v4 = *(const float4*)&sv[(k4i + j)*AP + 4*kg];
                float pj[4] = {(&p4[0].x)[j], (&p4[1].x)[j], (&p4[2].x)[j], (&p4[3].x)[j]};
#pragma unroll
                for (int u = 0; u < 4; u++) {
                    acc[u][0] = fmaf(pj[u], v4.x, acc[u][0]);
                    acc[u][1] = fmaf(pj[u], v4.y, acc[u][1]);
                    acc[u][2] = fmaf(pj[u], v4.z, acc[u][2]);
                    acc[u][3] = fmaf(pj[u], v4.w, acc[u][3]);
                }
            }
        }
        __syncwarp();
    }
#pragma unroll
    for (int u = 0; u < 4; u++) {
        float invl = 1.0f / l[u];
#pragma unroll
        for (int w = 0; w < 4; w++) {
            float y = acc[u][w] * invl;
            size_t o = ((size_t)(b*NSEL + qt*64 + qg + 16*u))*HDIM + h*64 + 4*kg + w;
            __half hh, ll; f16split(y, &hh, &ll);
            g_hah[o] = hh; g_hal[o] = ll;
        }
    }
}

// ---------------- scatter ----------------
__global__ void scatter_kernel(float* __restrict__ out, const float* __restrict__ nullq) {
    int j = blockIdx.x & 1023, b = blockIdx.x >> 10;
    int i = g_idx[b*NSEL + j];
    float* orow = out + ((size_t)b*SEQ + i)*DIM;
    const float* hrow = g_ho + ((size_t)(b*NSEL + j))*DIM;
    for (int d = threadIdx.x; d < DIM; d += 256)
        orow[d] += hrow[d] - nullq[d];
}

// ---------------- launch ----------------
extern "C" void kernel_launch(void* const* d_in, const int* in_sizes, int n_in,
                              void* d_out, int out_size) {
    const float* x       = (const float*)d_in[0];
    const float* ln_g    = (const float*)d_in[1];
    const float* ln_b    = (const float*)d_in[2];
    const float* qkv_w   = (const float*)d_in[3];
    const float* lout_w  = (const float*)d_in[4];
    const float* q_tok   = (const float*)d_in[5];
    const float* kv_tok  = (const float*)d_in[6];
    const float* hgamma  = (const float*)d_in[7];
    const float* hq_w    = (const float*)d_in[8];
    const float* hkv_w   = (const float*)d_in[9];
    const float* hnullkv = (const float*)d_in[10];
    const float* hout_w  = (const float*)d_in[11];
    const float* nullq   = (const float*)d_in[12];
    float* out = (float*)d_out;

    static cudaStream_t s2 = nullptr;
    static cudaEvent_t evFork = nullptr, evJoin = nullptr;
    if (!s2) {
        cudaStreamCreateWithFlags(&s2, cudaStreamNonBlocking);
        cudaEventCreateWithFlags(&evFork, cudaEventDisableTiming);
        cudaEventCreateWithFlags(&evJoin, cudaEventDisableTiming);
    }

    float *p_qkv, *p_qh, *p_kv, *p_ho;
    __half *p_xnh, *p_xnl, *p_lah, *p_lal, *p_rth, *p_rtl, *p_hah, *p_hal;
    __half *p_wqh, *p_wlh, *p_whqh, *p_wkh, *p_woh;
    cudaGetSymbolAddress((void**)&p_qkv, g_qkv);
    cudaGetSymbolAddress((void**)&p_qh, g_qh);
    cudaGetSymbolAddress((void**)&p_kv, g_kv);
    cudaGetSymbolAddress((void**)&p_ho, g_ho);
    cudaGetSymbolAddress((void**)&p_xnh, g_xnh); cudaGetSymbolAddress((void**)&p_xnl, g_xnl);
    cudaGetSymbolAddress((void**)&p_lah, g_lah); cudaGetSymbolAddress((void**)&p_lal, g_lal);
    cudaGetSymbolAddress((void**)&p_rth, g_rth); cudaGetSymbolAddress((void**)&p_rtl, g_rtl);
    cudaGetSymbolAddress((void**)&p_hah, g_hah); cudaGetSymbolAddress((void**)&p_hal, g_hal);
    cudaGetSymbolAddress((void**)&p_wqh, w_qkvh);
    cudaGetSymbolAddress((void**)&p_wlh, w_louth);
    cudaGetSymbolAddress((void**)&p_whqh, w_hqh);
    cudaGetSymbolAddress((void**)&p_wkh, w_hkvh);
    cudaGetSymbolAddress((void**)&p_woh, w_houth);

    const int LSMEM = 4*64*AP*4;
    const int HSMEM = 4*64*AP*4;
    const int RSMEM = SEQ*8 + 2*SEQ*4;
    const int GSMEM = 49152 + 1024;
    cudaFuncSetAttribute(light_attn_kernel,  cudaFuncAttributeMaxDynamicSharedMemorySize, LSMEM);
    cudaFuncSetAttribute(heavy_attn_kernel,  cudaFuncAttributeMaxDynamicSharedMemorySize, HSMEM);
    cudaFuncSetAttribute(route_select_kernel, cudaFuncAttributeMaxDynamicSharedMemorySize, RSMEM);
    cudaFuncSetAttribute(bmm_kernel, cudaFuncAttributeMaxDynamicSharedMemorySize, GSMEM);

    cudaEventRecord(evFork, 0);
    cudaStreamWaitEvent(s2, evFork, 0);

    // ======== stream 0: light path ========
    wprep_t_kernel<<<dim3(DIM/32, QKVD/32), dim3(32,8)>>>(qkv_w, p_wqh, DIM, QKVD);
    ln_kernel<<<BATCH*SEQ, 256>>>(x, ln_g, ln_b);
    bmm_kernel<<<dim3(QKVD/128, (BATCH*SEQ)/128), 256, GSMEM>>>(
        p_xnh, p_xnl, p_wqh, p_qkv, BATCH*SEQ, QKVD, DIM, nullptr);
    light_attn_kernel<<<dim3(NWIN, HEADS, BATCH), 256, LSMEM>>>();
    wprep_t_kernel<<<dim3(HDIM/32, DIM/32), dim3(32,8)>>>(lout_w, p_wlh, HDIM, DIM);
    bmm_kernel<<<dim3(DIM/128, (BATCH*SEQ)/128), 256, GSMEM>>>(
        p_lah, p_lal, p_wlh, out, BATCH*SEQ, DIM, HDIM, nullq);

    // ======== stream s2: routing + heavy path ========
    wprep_kernel<<<(DIM*DIM + 255)/256, 256, 0, s2>>>(hkv_w, p_wkh, DIM*DIM);
    wprep_t_kernel<<<dim3(DIM/32, HDIM/32), dim3(32,8), 0, s2>>>(hq_w, p_whqh, DIM, HDIM);
    wprep_t_kernel<<<dim3(HDIM/32, DIM/32), dim3(32,8), 0, s2>>>(hout_w, p_woh, HDIM, DIM);
    route_score_kernel<<<BATCH*SEQ, 256, 0, s2>>>(x, q_tok, kv_tok);
    route_select_kernel<<<dim3(BATCH, 2), 1024, RSMEM, s2>>>();
    gather_rms_kernel<<<dim3(NSEL, BATCH, 2), 256, 0, s2>>>(x, hgamma);
    bmm_kernel<<<dim3(HDIM/128, (BATCH*NSEL)/128), 256, GSMEM, s2>>>(
        p_rth, p_rtl, p_whqh, p_qh, BATCH*NSEL, HDIM, DIM, nullptr);
    rope_q_kernel<<<(BATCH*NSEL*HEADS*32)/256, 256, 0, s2>>>();
    bmm_kernel<<<dim3(DIM/128, (BATCH*NSEL)/128), 256, GSMEM, s2>>>(
        p_rth + (size_t)BATCH*NSEL*DIM, p_rtl + (size_t)BATCH*NSEL*DIM,
        p_wkh, p_kv, BATCH*NSEL, DIM, DIM, nullptr);
    pack_kv_kernel<<<(BATCH*HEADS*KVLEN*32 + 255)/256, 256, 0, s2>>>(hnullkv);
    heavy_attn_kernel<<<dim3(16, HEADS, BATCH), 256, HSMEM, s2>>>();
    bmm_kernel<<<dim3(DIM/128, (BATCH*NSEL)/128), 256, GSMEM, s2>>>(
        p_hah, p_hal, p_woh, p_ho, BATCH*NSEL, DIM, HDIM, nullptr);

    cudaEventRecord(evJoin, s2);
    cudaStreamWaitEvent(0, evJoin, 0);
    scatter_kernel<<<BATCH*NSEL, 256>>>(out, nullq);
}